// round 1
// baseline (speedup 1.0000x reference)
#include <cuda_runtime.h>
#include <cuda_bf16.h>

// Problem constants
#define B_    2
#define T_    2048
#define D_    4096
#define H_    32
#define KVH_  8
#define DH_   128
#define QS_   (H_*DH_)          // 4096
#define KS_   (KVH_*DH_)        // 1024
#define QKVN_ (QS_ + 2*KS_)     // 6144
#define M_    (B_*T_)           // 4096

// Scratch (allocation-free rule: static __device__ globals)
__device__ float g_qkv[(size_t)M_ * QKVN_];   // ~100.7 MB
__device__ float g_y[(size_t)M_ * QS_];       // ~67 MB

// ----------------------------------------------------------------------------
// Generic NT GEMM: C[M][N] = A[M][K] * B[N][K]^T  (all row-major, K%16==0,
// M%128==0, N%128==0). 128x128 tile, BK=16, 256 threads, 8x8 per thread.
// ----------------------------------------------------------------------------
__global__ __launch_bounds__(256, 2) void gemm_nt_kernel(
    const float* __restrict__ A, const float* __restrict__ Bm,
    float* __restrict__ C, int M, int N, int K)
{
    __shared__ float As[16][128];
    __shared__ float Bs[16][128];

    const int tid = threadIdx.x;
    const int tx  = tid & 15;        // 0..15 (cols)
    const int ty  = tid >> 4;        // 0..15 (rows)
    const int bm  = blockIdx.y * 128;
    const int bn  = blockIdx.x * 128;

    float acc[8][8];
#pragma unroll
    for (int i = 0; i < 8; i++)
#pragma unroll
        for (int j = 0; j < 8; j++) acc[i][j] = 0.0f;

    for (int kt = 0; kt < K; kt += 16) {
#pragma unroll
        for (int i = 0; i < 2; i++) {
            int idx = tid + i * 256;          // 0..511
            int row = idx >> 2;               // 0..127
            int c4  = (idx & 3) << 2;         // 0,4,8,12
            float4 va = *(const float4*)&A[(size_t)(bm + row) * K + kt + c4];
            As[c4 + 0][row] = va.x; As[c4 + 1][row] = va.y;
            As[c4 + 2][row] = va.z; As[c4 + 3][row] = va.w;
            float4 vb = *(const float4*)&Bm[(size_t)(bn + row) * K + kt + c4];
            Bs[c4 + 0][row] = vb.x; Bs[c4 + 1][row] = vb.y;
            Bs[c4 + 2][row] = vb.z; Bs[c4 + 3][row] = vb.w;
        }
        __syncthreads();

#pragma unroll
        for (int k = 0; k < 16; k++) {
            float a[8], b[8];
            *(float4*)&a[0] = *(const float4*)&As[k][4 * ty];
            *(float4*)&a[4] = *(const float4*)&As[k][4 * ty + 64];
            *(float4*)&b[0] = *(const float4*)&Bs[k][4 * tx];
            *(float4*)&b[4] = *(const float4*)&Bs[k][4 * tx + 64];
#pragma unroll
            for (int i = 0; i < 8; i++)
#pragma unroll
                for (int j = 0; j < 8; j++)
                    acc[i][j] += a[i] * b[j];
        }
        __syncthreads();
    }

#pragma unroll
    for (int i = 0; i < 8; i++) {
        int r = bm + ((i < 4) ? (4 * ty + i) : (64 + 4 * ty + i - 4));
        float4 v0 = make_float4(acc[i][0], acc[i][1], acc[i][2], acc[i][3]);
        float4 v1 = make_float4(acc[i][4], acc[i][5], acc[i][6], acc[i][7]);
        *(float4*)&C[(size_t)r * N + bn + 4 * tx]      = v0;
        *(float4*)&C[(size_t)r * N + bn + 64 + 4 * tx] = v1;
    }
}

// ----------------------------------------------------------------------------
// RoPE in-place on g_qkv (Q heads + K heads), interleaved-pair convention.
// ----------------------------------------------------------------------------
__global__ void rope_kernel(const float* __restrict__ pcos,
                            const float* __restrict__ psin)
{
    int idx = blockIdx.x * blockDim.x + threadIdx.x;
    const int total = M_ * (H_ + KVH_) * (DH_ / 2);
    if (idx >= total) return;
    int i  = idx & 63;                       // pair index 0..63
    int h  = (idx >> 6) % (H_ + KVH_);
    int bt = idx / (64 * (H_ + KVH_));
    int t  = bt & (T_ - 1);
    float c = pcos[t * 64 + i];
    float s = psin[t * 64 + i];
    size_t base = (size_t)bt * QKVN_ +
                  ((h < H_) ? (h * DH_) : (QS_ + (h - H_) * DH_)) + 2 * i;
    float v0 = g_qkv[base];
    float v1 = g_qkv[base + 1];
    g_qkv[base]     = v0 * c - v1 * s;
    g_qkv[base + 1] = v0 * s + v1 * c;
}

// ----------------------------------------------------------------------------
// Flash-style causal attention with GQA (reads g_qkv directly, writes g_y).
// Grid: (T/64, H, B). 256 threads = 8 warps; each warp owns 8 query rows.
// Lane owns S cols {lane, lane+32}; O cols {lane + 32*j, j=0..3}.
// smem: sQ(64x132) | sK(64x132, aliased as P after S) | sV(64x132)
// ----------------------------------------------------------------------------
#define PAD_ 132
#define ATTN_SMEM (3 * 64 * PAD_ * sizeof(float))

__global__ __launch_bounds__(256, 2) void attn_kernel(float* __restrict__ y)
{
    extern __shared__ float sm[];
    float* sQ = sm;
    float* sK = sQ + 64 * PAD_;
    float* sV = sK + 64 * PAD_;
    float* sP = sK;   // alias: K tile is dead once S is computed

    const int tid  = threadIdx.x;
    const int lane = tid & 31;
    const int w    = tid >> 5;
    const int row0 = w * 8;

    const int qb = blockIdx.x * 64;
    const int h  = blockIdx.y;
    const int b  = blockIdx.z;
    const int kh = h >> 2;    // GQA: 4 query heads per kv head

    const float* qptr = g_qkv + (size_t)b * T_ * QKVN_ + h * DH_;
    const float* kptr = g_qkv + (size_t)b * T_ * QKVN_ + QS_ + kh * DH_;
    const float* vptr = kptr + KS_;

    // Load Q tile
    for (int i = tid; i < 64 * 32; i += 256) {
        int r  = i >> 5;
        int c4 = (i & 31) << 2;
        *(float4*)&sQ[r * PAD_ + c4] =
            *(const float4*)&qptr[(size_t)(qb + r) * QKVN_ + c4];
    }

    float m_r[8], l_r[8], O[8][4];
#pragma unroll
    for (int r = 0; r < 8; r++) {
        m_r[r] = -1e30f; l_r[r] = 0.0f;
#pragma unroll
        for (int j = 0; j < 4; j++) O[r][j] = 0.0f;
    }

    const float scale = 0.08838834764831845f;   // 1/sqrt(128)
    const int nkb = (qb >> 6) + 1;

    for (int kb = 0; kb < nkb; kb++) {
        // Cooperative K/V tile load
        for (int i = tid; i < 64 * 32; i += 256) {
            int r  = i >> 5;
            int c4 = (i & 31) << 2;
            size_t grow = (size_t)(kb * 64 + r) * QKVN_ + c4;
            *(float4*)&sK[r * PAD_ + c4] = *(const float4*)&kptr[grow];
            *(float4*)&sV[r * PAD_ + c4] = *(const float4*)&vptr[grow];
        }
        __syncthreads();

        // S = Q K^T for this warp's 8 rows, lane cols {lane, lane+32}
        float S[8][2];
#pragma unroll
        for (int r = 0; r < 8; r++) { S[r][0] = 0.0f; S[r][1] = 0.0f; }

        for (int k = 0; k < DH_; k += 4) {
            float4 k0 = *(const float4*)&sK[lane * PAD_ + k];
            float4 k1 = *(const float4*)&sK[(lane + 32) * PAD_ + k];
#pragma unroll
            for (int r = 0; r < 8; r++) {
                float4 q = *(const float4*)&sQ[(row0 + r) * PAD_ + k];
                S[r][0] += q.x * k0.x + q.y * k0.y + q.z * k0.z + q.w * k0.w;
                S[r][1] += q.x * k1.x + q.y * k1.y + q.z * k1.z + q.w * k1.w;
            }
        }
        __syncthreads();   // everyone done reading sK before P overwrites it

        const bool diag = (kb == (qb >> 6));
#pragma unroll
        for (int r = 0; r < 8; r++) {
            int qrow = qb + row0 + r;
            float s0 = S[r][0] * scale;
            float s1 = S[r][1] * scale;
            if (diag) {
                if (kb * 64 + lane      > qrow) s0 = -1e30f;
                if (kb * 64 + lane + 32 > qrow) s1 = -1e30f;
            }
            float mx = fmaxf(s0, s1);
#pragma unroll
            for (int o = 16; o > 0; o >>= 1)
                mx = fmaxf(mx, __shfl_xor_sync(0xffffffffu, mx, o));
            float mnew = fmaxf(m_r[r], mx);
            float p0 = __expf(s0 - mnew);
            float p1 = __expf(s1 - mnew);
            float corr = __expf(m_r[r] - mnew);
            float ps = p0 + p1;
#pragma unroll
            for (int o = 16; o > 0; o >>= 1)
                ps += __shfl_xor_sync(0xffffffffu, ps, o);
            l_r[r] = l_r[r] * corr + ps;
            m_r[r] = mnew;
#pragma unroll
            for (int j = 0; j < 4; j++) O[r][j] *= corr;
            sP[(row0 + r) * 64 + lane]      = p0;
            sP[(row0 + r) * 64 + lane + 32] = p1;
        }
        __syncwarp();   // P is warp-private (rows disjoint per warp)

        // O += P * V
#pragma unroll 4
        for (int j = 0; j < 64; j++) {
            float v0 = sV[j * PAD_ + lane];
            float v1 = sV[j * PAD_ + lane + 32];
            float v2 = sV[j * PAD_ + lane + 64];
            float v3 = sV[j * PAD_ + lane + 96];
#pragma unroll
            for (int r = 0; r < 8; r++) {
                float p = sP[(row0 + r) * 64 + j];
                O[r][0] += p * v0;
                O[r][1] += p * v1;
                O[r][2] += p * v2;
                O[r][3] += p * v3;
            }
        }
        __syncthreads();   // done with sP/sV before next tile load
    }

    // Epilogue: normalize and write y[b, t, h*128 + c]
#pragma unroll
    for (int r = 0; r < 8; r++) {
        float inv = 1.0f / l_r[r];
        int t = qb + row0 + r;
        size_t base = ((size_t)(b * T_ + t)) * QS_ + h * DH_;
        y[base + lane]      = O[r][0] * inv;
        y[base + lane + 32] = O[r][1] * inv;
        y[base + lane + 64] = O[r][2] * inv;
        y[base + lane + 96] = O[r][3] * inv;
    }
}

// ----------------------------------------------------------------------------
extern "C" void kernel_launch(void* const* d_in, const int* in_sizes, int n_in,
                              void* d_out, int out_size)
{
    const float* x    = (const float*)d_in[0];
    const float* fcos = (const float*)d_in[1];
    const float* fsin = (const float*)d_in[2];
    const float* wqkv = (const float*)d_in[3];
    const float* wo   = (const float*)d_in[4];
    float* out = (float*)d_out;

    float* qkv = nullptr;
    float* yb  = nullptr;
    cudaGetSymbolAddress((void**)&qkv, g_qkv);
    cudaGetSymbolAddress((void**)&yb,  g_y);

    // 1) qkv = x @ w_qkv^T
    gemm_nt_kernel<<<dim3(QKVN_ / 128, M_ / 128), 256>>>(x, wqkv, qkv, M_, QKVN_, D_);

    // 2) RoPE in-place on q,k slices
    {
        int total = M_ * (H_ + KVH_) * (DH_ / 2);
        rope_kernel<<<(total + 255) / 256, 256>>>(fcos, fsin);
    }

    // 3) Causal GQA flash attention -> y
    cudaFuncSetAttribute(attn_kernel, cudaFuncAttributeMaxDynamicSharedMemorySize,
                         (int)ATTN_SMEM);
    attn_kernel<<<dim3(T_ / 64, H_, B_), 256, ATTN_SMEM>>>(yb);

    // 4) out = y @ wo^T
    gemm_nt_kernel<<<dim3(D_ / 128, M_ / 128), 256>>>(yb, wo, out, M_, D_, QS_);
}

// round 3
// speedup vs baseline: 1.7448x; 1.7448x over previous
#include <cuda_runtime.h>
#include <cuda_bf16.h>
#include <cstdint>

// Problem constants
#define B_    2
#define T_    2048
#define D_    4096
#define H_    32
#define KVH_  8
#define DH_   128
#define QS_   (H_*DH_)          // 4096
#define KS_   (KVH_*DH_)        // 1024
#define QKVN_ (QS_ + 2*KS_)     // 6144
#define M_    (B_*T_)           // 4096

// Scratch (allocation-free rule: static __device__ globals)
__device__ float g_qkv[(size_t)M_ * QKVN_];
__device__ float g_y[(size_t)M_ * QS_];
__device__ __nv_bfloat16 g_xh[(size_t)M_ * D_];
__device__ __nv_bfloat16 g_xl[(size_t)M_ * D_];
__device__ __nv_bfloat16 g_wh[(size_t)QKVN_ * D_];
__device__ __nv_bfloat16 g_wl[(size_t)QKVN_ * D_];
__device__ __nv_bfloat16 g_yh[(size_t)M_ * QS_];
__device__ __nv_bfloat16 g_yl[(size_t)M_ * QS_];
__device__ __nv_bfloat16 g_oh[(size_t)D_ * QS_];
__device__ __nv_bfloat16 g_ol[(size_t)D_ * QS_];

// ---------------------------------------------------------------------------
// PTX helpers (sm_80-era ISA only: cp.async, ldmatrix, mma.sync — all legal
// at the compute_103 family target the harness compiles to)
// ---------------------------------------------------------------------------
__device__ __forceinline__ uint32_t smem_u32(const void* p) {
    uint32_t a;
    asm("{ .reg .u64 t; cvta.to.shared.u64 t, %1; cvt.u32.u64 %0, t; }"
        : "=r"(a) : "l"(p));
    return a;
}
__device__ __forceinline__ void cpasync16(uint32_t s, const void* g) {
    asm volatile("cp.async.cg.shared.global [%0], [%1], 16;" :: "r"(s), "l"(g));
}
#define CP_COMMIT() asm volatile("cp.async.commit_group;" ::: "memory")
#define CP_WAIT(N)  asm volatile("cp.async.wait_group %0;" :: "n"(N) : "memory")

#define LDSM_X4(r, addr)                                                      \
    asm volatile("ldmatrix.sync.aligned.m8n8.x4.shared.b16 {%0,%1,%2,%3}, [%4];" \
        : "=r"((r)[0]), "=r"((r)[1]), "=r"((r)[2]), "=r"((r)[3]) : "r"(addr))

#define MMA16816(d, a, b0, b1)                                                \
    asm volatile("mma.sync.aligned.m16n8k16.row.col.f32.bf16.bf16.f32 "       \
        "{%0,%1,%2,%3}, {%4,%5,%6,%7}, {%8,%9}, {%0,%1,%2,%3};"               \
        : "+f"((d)[0]), "+f"((d)[1]), "+f"((d)[2]), "+f"((d)[3])              \
        : "r"((a)[0]), "r"((a)[1]), "r"((a)[2]), "r"((a)[3]), "r"(b0), "r"(b1))

// ---------------------------------------------------------------------------
// 3xBF16 mma.sync GEMM:  C[M][N] = A[M][K] * B[N][K]^T  (fp32 out)
// A,B as bf16 hi/lo planes, row-major [rows][K], K % 32 == 0.
// CTA 128x128, BK=32, 256 thr, warp grid 4(M)x2(N), warp tile 32x64.
// smem row stride 40 elems (80 B) -> conflict-free ldmatrix.
// ---------------------------------------------------------------------------
#define GST_ 40                      // smem row stride, elements
#define PLANE_ (128 * GST_ * 2)      // 10240 B per plane
#define STAGE_ (4 * PLANE_)          // 40960 B per stage
#define GSMEM_ (2 * STAGE_)          // 81920 B

__global__ __launch_bounds__(256, 1) void gemm3bf16_kernel(
    const __nv_bfloat16* __restrict__ Ah, const __nv_bfloat16* __restrict__ Al,
    const __nv_bfloat16* __restrict__ Bh, const __nv_bfloat16* __restrict__ Bl,
    float* __restrict__ C, int M, int N, int K)
{
    extern __shared__ char smem[];
    const uint32_t sbase = smem_u32(smem);
    const int tid  = threadIdx.x;
    const int lane = tid & 31;
    const int wid  = tid >> 5;
    const int wm   = wid >> 1;        // 0..3
    const int wn   = wid & 1;         // 0..1

    const int bm = blockIdx.y * 128;
    const int bn = blockIdx.x * 128;
    const int nk = K >> 5;

    const __nv_bfloat16* gp[4] = {
        Ah + (size_t)bm * K, Al + (size_t)bm * K,
        Bh + (size_t)bn * K, Bl + (size_t)bn * K };

    // loader precompute: this thread's two (row,seg) chunks per plane
    const int row0c = tid >> 2, seg0 = tid & 3;           // chunk tid
    const int row1c = (tid + 256) >> 2, seg1 = tid & 3;   // chunk tid+256

    float acc[2][8][4];
#pragma unroll
    for (int mt = 0; mt < 2; mt++)
#pragma unroll
        for (int nt = 0; nt < 8; nt++)
#pragma unroll
            for (int q = 0; q < 4; q++) acc[mt][nt][q] = 0.0f;

    // ---- prologue: async-load chunk 0 into stage 0
    {
        const int k0 = 0;
#pragma unroll
        for (int p = 0; p < 4; p++) {
            uint32_t sb = sbase + p * PLANE_;
            cpasync16(sb + row0c * 80 + seg0 * 16,
                      (const char*)(gp[p] + (size_t)row0c * K + k0) + seg0 * 16);
            cpasync16(sb + row1c * 80 + seg1 * 16,
                      (const char*)(gp[p] + (size_t)row1c * K + k0) + seg1 * 16);
        }
        CP_COMMIT();
    }

    // frag address components
    const int rowA = lane & 15;
    const int colA = (lane >> 4) * 16;            // bytes
    const int rowB = (lane & 7) + ((lane & 16) ? 8 : 0);
    const int colB = ((lane >> 3) & 1) * 16;      // bytes

    for (int c = 0; c < nk; c++) {
        const int cur = c & 1;
        if (c + 1 < nk) {
            const int k0 = (c + 1) << 5;
            const uint32_t st = sbase + (cur ^ 1) * STAGE_;
#pragma unroll
            for (int p = 0; p < 4; p++) {
                uint32_t sb = st + p * PLANE_;
                cpasync16(sb + row0c * 80 + seg0 * 16,
                          (const char*)(gp[p] + (size_t)row0c * K + k0) + seg0 * 16);
                cpasync16(sb + row1c * 80 + seg1 * 16,
                          (const char*)(gp[p] + (size_t)row1c * K + k0) + seg1 * 16);
            }
            CP_COMMIT();
            CP_WAIT(1);
        } else {
            CP_WAIT(0);
        }
        __syncthreads();

        const uint32_t st   = sbase + cur * STAGE_;
        const uint32_t sA_h = st;
        const uint32_t sA_l = st + PLANE_;
        const uint32_t sB_h = st + 2 * PLANE_;
        const uint32_t sB_l = st + 3 * PLANE_;

#pragma unroll
        for (int ks = 0; ks < 2; ks++) {
            const int kb = ks * 32;   // bytes within row (16 bf16)
            uint32_t ah[2][4], al[2][4], bh[4][4], bl[4][4];
#pragma unroll
            for (int mt = 0; mt < 2; mt++) {
                uint32_t off = (uint32_t)((wm * 32 + mt * 16 + rowA) * 80 + colA + kb);
                LDSM_X4(ah[mt], sA_h + off);
                LDSM_X4(al[mt], sA_l + off);
            }
#pragma unroll
            for (int np = 0; np < 4; np++) {
                uint32_t off = (uint32_t)((wn * 64 + np * 16 + rowB) * 80 + colB + kb);
                LDSM_X4(bh[np], sB_h + off);
                LDSM_X4(bl[np], sB_l + off);
            }
#pragma unroll
            for (int mt = 0; mt < 2; mt++)
#pragma unroll
                for (int nt = 0; nt < 8; nt++) {
                    const uint32_t* ph = &bh[nt >> 1][(nt & 1) * 2];
                    const uint32_t* pl = &bl[nt >> 1][(nt & 1) * 2];
                    MMA16816(acc[mt][nt], ah[mt], ph[0], ph[1]);
                    MMA16816(acc[mt][nt], ah[mt], pl[0], pl[1]);
                    MMA16816(acc[mt][nt], al[mt], ph[0], ph[1]);
                }
        }
        __syncthreads();
    }

    // epilogue
#pragma unroll
    for (int mt = 0; mt < 2; mt++) {
        const int r0 = bm + wm * 32 + mt * 16 + (lane >> 2);
#pragma unroll
        for (int nt = 0; nt < 8; nt++) {
            const int col = bn + wn * 64 + nt * 8 + (lane & 3) * 2;
            *(float2*)&C[(size_t)r0 * N + col] =
                make_float2(acc[mt][nt][0], acc[mt][nt][1]);
            *(float2*)&C[(size_t)(r0 + 8) * N + col] =
                make_float2(acc[mt][nt][2], acc[mt][nt][3]);
        }
    }
}

// ---------------------------------------------------------------------------
// Split fp32 -> bf16 hi + bf16 lo planes
// ---------------------------------------------------------------------------
__global__ void split_kernel(const float* __restrict__ in,
                             __nv_bfloat16* __restrict__ hi,
                             __nv_bfloat16* __restrict__ lo, int n4)
{
    int idx = blockIdx.x * blockDim.x + threadIdx.x;
    if (idx >= n4) return;
    float4 v = ((const float4*)in)[idx];
    __nv_bfloat16 h0 = __float2bfloat16(v.x);
    __nv_bfloat16 h1 = __float2bfloat16(v.y);
    __nv_bfloat16 h2 = __float2bfloat16(v.z);
    __nv_bfloat16 h3 = __float2bfloat16(v.w);
    __nv_bfloat16 l0 = __float2bfloat16(v.x - __bfloat162float(h0));
    __nv_bfloat16 l1 = __float2bfloat16(v.y - __bfloat162float(h1));
    __nv_bfloat16 l2 = __float2bfloat16(v.z - __bfloat162float(h2));
    __nv_bfloat16 l3 = __float2bfloat16(v.w - __bfloat162float(h3));
    __nv_bfloat162* hp = (__nv_bfloat162*)(hi + (size_t)idx * 4);
    __nv_bfloat162* lp = (__nv_bfloat162*)(lo + (size_t)idx * 4);
    hp[0] = __nv_bfloat162(h0, h1); hp[1] = __nv_bfloat162(h2, h3);
    lp[0] = __nv_bfloat162(l0, l1); lp[1] = __nv_bfloat162(l2, l3);
}

// ----------------------------------------------------------------------------
// RoPE in-place on g_qkv (Q heads + K heads), interleaved-pair convention.
// ----------------------------------------------------------------------------
__global__ void rope_kernel(const float* __restrict__ pcos,
                            const float* __restrict__ psin)
{
    int idx = blockIdx.x * blockDim.x + threadIdx.x;
    const int total = M_ * (H_ + KVH_) * (DH_ / 2);
    if (idx >= total) return;
    int i  = idx & 63;
    int h  = (idx >> 6) % (H_ + KVH_);
    int bt = idx / (64 * (H_ + KVH_));
    int t  = bt & (T_ - 1);
    float c = pcos[t * 64 + i];
    float s = psin[t * 64 + i];
    size_t base = (size_t)bt * QKVN_ +
                  ((h < H_) ? (h * DH_) : (QS_ + (h - H_) * DH_)) + 2 * i;
    float v0 = g_qkv[base];
    float v1 = g_qkv[base + 1];
    g_qkv[base]     = v0 * c - v1 * s;
    g_qkv[base + 1] = v0 * s + v1 * c;
}

// ----------------------------------------------------------------------------
// Flash-style causal attention with GQA (reads g_qkv directly, writes g_y).
// ----------------------------------------------------------------------------
#define PAD_ 132
#define ATTN_SMEM (3 * 64 * PAD_ * sizeof(float))

__global__ __launch_bounds__(256, 2) void attn_kernel(float* __restrict__ y)
{
    extern __shared__ float sm[];
    float* sQ = sm;
    float* sK = sQ + 64 * PAD_;
    float* sV = sK + 64 * PAD_;
    float* sP = sK;

    const int tid  = threadIdx.x;
    const int lane = tid & 31;
    const int w    = tid >> 5;
    const int row0 = w * 8;

    const int qb = blockIdx.x * 64;
    const int h  = blockIdx.y;
    const int b  = blockIdx.z;
    const int kh = h >> 2;

    const float* qptr = g_qkv + (size_t)b * T_ * QKVN_ + h * DH_;
    const float* kptr = g_qkv + (size_t)b * T_ * QKVN_ + QS_ + kh * DH_;
    const float* vptr = kptr + KS_;

    for (int i = tid; i < 64 * 32; i += 256) {
        int r  = i >> 5;
        int c4 = (i & 31) << 2;
        *(float4*)&sQ[r * PAD_ + c4] =
            *(const float4*)&qptr[(size_t)(qb + r) * QKVN_ + c4];
    }

    float m_r[8], l_r[8], O[8][4];
#pragma unroll
    for (int r = 0; r < 8; r++) {
        m_r[r] = -1e30f; l_r[r] = 0.0f;
#pragma unroll
        for (int j = 0; j < 4; j++) O[r][j] = 0.0f;
    }

    const float scale = 0.08838834764831845f;
    const int nkb = (qb >> 6) + 1;

    for (int kb = 0; kb < nkb; kb++) {
        for (int i = tid; i < 64 * 32; i += 256) {
            int r  = i >> 5;
            int c4 = (i & 31) << 2;
            size_t grow = (size_t)(kb * 64 + r) * QKVN_ + c4;
            *(float4*)&sK[r * PAD_ + c4] = *(const float4*)&kptr[grow];
            *(float4*)&sV[r * PAD_ + c4] = *(const float4*)&vptr[grow];
        }
        __syncthreads();

        float S[8][2];
#pragma unroll
        for (int r = 0; r < 8; r++) { S[r][0] = 0.0f; S[r][1] = 0.0f; }

        for (int k = 0; k < DH_; k += 4) {
            float4 k0 = *(const float4*)&sK[lane * PAD_ + k];
            float4 k1 = *(const float4*)&sK[(lane + 32) * PAD_ + k];
#pragma unroll
            for (int r = 0; r < 8; r++) {
                float4 q = *(const float4*)&sQ[(row0 + r) * PAD_ + k];
                S[r][0] += q.x * k0.x + q.y * k0.y + q.z * k0.z + q.w * k0.w;
                S[r][1] += q.x * k1.x + q.y * k1.y + q.z * k1.z + q.w * k1.w;
            }
        }
        __syncthreads();

        const bool diag = (kb == (qb >> 6));
#pragma unroll
        for (int r = 0; r < 8; r++) {
            int qrow = qb + row0 + r;
            float s0 = S[r][0] * scale;
            float s1 = S[r][1] * scale;
            if (diag) {
                if (kb * 64 + lane      > qrow) s0 = -1e30f;
                if (kb * 64 + lane + 32 > qrow) s1 = -1e30f;
            }
            float mx = fmaxf(s0, s1);
#pragma unroll
            for (int o = 16; o > 0; o >>= 1)
                mx = fmaxf(mx, __shfl_xor_sync(0xffffffffu, mx, o));
            float mnew = fmaxf(m_r[r], mx);
            float p0 = __expf(s0 - mnew);
            float p1 = __expf(s1 - mnew);
            float corr = __expf(m_r[r] - mnew);
            float ps = p0 + p1;
#pragma unroll
            for (int o = 16; o > 0; o >>= 1)
                ps += __shfl_xor_sync(0xffffffffu, ps, o);
            l_r[r] = l_r[r] * corr + ps;
            m_r[r] = mnew;
#pragma unroll
            for (int j = 0; j < 4; j++) O[r][j] *= corr;
            sP[(row0 + r) * 64 + lane]      = p0;
            sP[(row0 + r) * 64 + lane + 32] = p1;
        }
        __syncwarp();

#pragma unroll 4
        for (int j = 0; j < 64; j++) {
            float v0 = sV[j * PAD_ + lane];
            float v1 = sV[j * PAD_ + lane + 32];
            float v2 = sV[j * PAD_ + lane + 64];
            float v3 = sV[j * PAD_ + lane + 96];
#pragma unroll
            for (int r = 0; r < 8; r++) {
                float p = sP[(row0 + r) * 64 + j];
                O[r][0] += p * v0;
                O[r][1] += p * v1;
                O[r][2] += p * v2;
                O[r][3] += p * v3;
            }
        }
        __syncthreads();
    }

#pragma unroll
    for (int r = 0; r < 8; r++) {
        float inv = 1.0f / l_r[r];
        int t = qb + row0 + r;
        size_t base = ((size_t)(b * T_ + t)) * QS_ + h * DH_;
        y[base + lane]      = O[r][0] * inv;
        y[base + lane + 32] = O[r][1] * inv;
        y[base + lane + 64] = O[r][2] * inv;
        y[base + lane + 96] = O[r][3] * inv;
    }
}

// ----------------------------------------------------------------------------
extern "C" void kernel_launch(void* const* d_in, const int* in_sizes, int n_in,
                              void* d_out, int out_size)
{
    const float* x    = (const float*)d_in[0];
    const float* fcos = (const float*)d_in[1];
    const float* fsin = (const float*)d_in[2];
    const float* wqkv = (const float*)d_in[3];
    const float* wo   = (const float*)d_in[4];
    float* out = (float*)d_out;

    float *qkv = nullptr, *yb = nullptr;
    __nv_bfloat16 *xh, *xl, *wh, *wl, *yh, *yl, *oh, *ol;
    cudaGetSymbolAddress((void**)&qkv, g_qkv);
    cudaGetSymbolAddress((void**)&yb,  g_y);
    cudaGetSymbolAddress((void**)&xh,  g_xh);
    cudaGetSymbolAddress((void**)&xl,  g_xl);
    cudaGetSymbolAddress((void**)&wh,  g_wh);
    cudaGetSymbolAddress((void**)&wl,  g_wl);
    cudaGetSymbolAddress((void**)&yh,  g_yh);
    cudaGetSymbolAddress((void**)&yl,  g_yl);
    cudaGetSymbolAddress((void**)&oh,  g_oh);
    cudaGetSymbolAddress((void**)&ol,  g_ol);

    cudaFuncSetAttribute(gemm3bf16_kernel,
                         cudaFuncAttributeMaxDynamicSharedMemorySize, GSMEM_);
    cudaFuncSetAttribute(attn_kernel,
                         cudaFuncAttributeMaxDynamicSharedMemorySize, (int)ATTN_SMEM);

    // 1) split x and w_qkv to bf16 hi/lo planes
    {
        int n4 = (M_ * D_) / 4;
        split_kernel<<<(n4 + 255) / 256, 256>>>(x, xh, xl, n4);
        n4 = (QKVN_ * D_) / 4;
        split_kernel<<<(n4 + 255) / 256, 256>>>(wqkv, wh, wl, n4);
    }

    // 2) qkv = x @ w_qkv^T
    gemm3bf16_kernel<<<dim3(QKVN_ / 128, M_ / 128), 256, GSMEM_>>>(
        xh, xl, wh, wl, qkv, M_, QKVN_, D_);

    // 3) RoPE in-place
    {
        int total = M_ * (H_ + KVH_) * (DH_ / 2);
        rope_kernel<<<(total + 255) / 256, 256>>>(fcos, fsin);
    }

    // 4) Causal GQA flash attention -> y
    attn_kernel<<<dim3(T_ / 64, H_, B_), 256, ATTN_SMEM>>>(yb);

    // 5) split y and wo
    {
        int n4 = (M_ * QS_) / 4;
        split_kernel<<<(n4 + 255) / 256, 256>>>(yb, yh, yl, n4);
        n4 = (D_ * QS_) / 4;
        split_kernel<<<(n4 + 255) / 256, 256>>>(wo, oh, ol, n4);
    }

    // 6) out = y @ wo^T
    gemm3bf16_kernel<<<dim3(D_ / 128, M_ / 128), 256, GSMEM_>>>(
        yh, yl, oh, ol, out, M_, D_, QS_);
}

// round 4
// speedup vs baseline: 1.7483x; 1.0020x over previous
#include <cuda_runtime.h>
#include <cuda_bf16.h>
#include <cstdint>

// Problem constants
#define B_    2
#define T_    2048
#define D_    4096
#define H_    32
#define KVH_  8
#define DH_   128
#define QS_   (H_*DH_)          // 4096
#define KS_   (KVH_*DH_)        // 1024
#define QKVN_ (QS_ + 2*KS_)     // 6144
#define M_    (B_*T_)           // 4096

// Scratch (allocation-free rule: static __device__ globals)
__device__ float g_qkv[(size_t)M_ * QKVN_];
__device__ float g_y[(size_t)M_ * QS_];
__device__ __nv_bfloat16 g_xh[(size_t)M_ * D_];
__device__ __nv_bfloat16 g_xl[(size_t)M_ * D_];
__device__ __nv_bfloat16 g_wh[(size_t)QKVN_ * D_];
__device__ __nv_bfloat16 g_wl[(size_t)QKVN_ * D_];
__device__ __nv_bfloat16 g_yh[(size_t)M_ * QS_];
__device__ __nv_bfloat16 g_yl[(size_t)M_ * QS_];
__device__ __nv_bfloat16 g_oh[(size_t)D_ * QS_];
__device__ __nv_bfloat16 g_ol[(size_t)D_ * QS_];

// ---------------------------------------------------------------------------
// PTX helpers (sm_80-era ISA only: cp.async, ldmatrix, mma.sync — all legal
// at the compute_103 family target the harness compiles to)
// ---------------------------------------------------------------------------
__device__ __forceinline__ uint32_t smem_u32(const void* p) {
    uint32_t a;
    asm("{ .reg .u64 t; cvta.to.shared.u64 t, %1; cvt.u32.u64 %0, t; }"
        : "=r"(a) : "l"(p));
    return a;
}
__device__ __forceinline__ void cpasync16(uint32_t s, const void* g) {
    asm volatile("cp.async.cg.shared.global [%0], [%1], 16;" :: "r"(s), "l"(g));
}
#define CP_COMMIT() asm volatile("cp.async.commit_group;" ::: "memory")
#define CP_WAIT(N)  asm volatile("cp.async.wait_group %0;" :: "n"(N) : "memory")

#define LDSM_X4(r, addr)                                                      \
    asm volatile("ldmatrix.sync.aligned.m8n8.x4.shared.b16 {%0,%1,%2,%3}, [%4];" \
        : "=r"((r)[0]), "=r"((r)[1]), "=r"((r)[2]), "=r"((r)[3]) : "r"(addr))

#define MMA16816(d, a, b0, b1)                                                \
    asm volatile("mma.sync.aligned.m16n8k16.row.col.f32.bf16.bf16.f32 "       \
        "{%0,%1,%2,%3}, {%4,%5,%6,%7}, {%8,%9}, {%0,%1,%2,%3};"               \
        : "+f"((d)[0]), "+f"((d)[1]), "+f"((d)[2]), "+f"((d)[3])              \
        : "r"((a)[0]), "r"((a)[1]), "r"((a)[2]), "r"((a)[3]), "r"(b0), "r"(b1))

// ---------------------------------------------------------------------------
// 3xBF16 mma.sync GEMM:  C[M][N] = A[M][K] * B[N][K]^T  (fp32 out)
// A,B as bf16 hi/lo planes, row-major [rows][K], K % 32 == 0.
// CTA 128x128, BK=32, 256 thr, warp grid 4(M)x2(N), warp tile 32x64.
// smem row stride 40 elems (80 B) -> conflict-free ldmatrix.
// ---------------------------------------------------------------------------
#define GST_ 40                      // smem row stride, elements
#define PLANE_ (128 * GST_ * 2)      // 10240 B per plane
#define STAGE_ (4 * PLANE_)          // 40960 B per stage
#define GSMEM_ (2 * STAGE_)          // 81920 B

__global__ __launch_bounds__(256, 1) void gemm3bf16_kernel(
    const __nv_bfloat16* __restrict__ Ah, const __nv_bfloat16* __restrict__ Al,
    const __nv_bfloat16* __restrict__ Bh, const __nv_bfloat16* __restrict__ Bl,
    float* __restrict__ C, int M, int N, int K)
{
    extern __shared__ char smem[];
    const uint32_t sbase = smem_u32(smem);
    const int tid  = threadIdx.x;
    const int lane = tid & 31;
    const int wid  = tid >> 5;
    const int wm   = wid >> 1;        // 0..3
    const int wn   = wid & 1;         // 0..1

    const int bm = blockIdx.y * 128;
    const int bn = blockIdx.x * 128;
    const int nk = K >> 5;

    const __nv_bfloat16* gp[4] = {
        Ah + (size_t)bm * K, Al + (size_t)bm * K,
        Bh + (size_t)bn * K, Bl + (size_t)bn * K };

    // loader precompute: this thread's two (row,seg) chunks per plane
    const int row0c = tid >> 2, seg0 = tid & 3;           // chunk tid
    const int row1c = (tid + 256) >> 2, seg1 = tid & 3;   // chunk tid+256

    float acc[2][8][4];
#pragma unroll
    for (int mt = 0; mt < 2; mt++)
#pragma unroll
        for (int nt = 0; nt < 8; nt++)
#pragma unroll
            for (int q = 0; q < 4; q++) acc[mt][nt][q] = 0.0f;

    // ---- prologue: async-load chunk 0 into stage 0
    {
        const int k0 = 0;
#pragma unroll
        for (int p = 0; p < 4; p++) {
            uint32_t sb = sbase + p * PLANE_;
            cpasync16(sb + row0c * 80 + seg0 * 16,
                      (const char*)(gp[p] + (size_t)row0c * K + k0) + seg0 * 16);
            cpasync16(sb + row1c * 80 + seg1 * 16,
                      (const char*)(gp[p] + (size_t)row1c * K + k0) + seg1 * 16);
        }
        CP_COMMIT();
    }

    // frag address components
    const int rowA = lane & 15;
    const int colA = (lane >> 4) * 16;            // bytes
    const int rowB = (lane & 7) + ((lane & 16) ? 8 : 0);
    const int colB = ((lane >> 3) & 1) * 16;      // bytes

    for (int c = 0; c < nk; c++) {
        const int cur = c & 1;
        if (c + 1 < nk) {
            const int k0 = (c + 1) << 5;
            const uint32_t st = sbase + (cur ^ 1) * STAGE_;
#pragma unroll
            for (int p = 0; p < 4; p++) {
                uint32_t sb = st + p * PLANE_;
                cpasync16(sb + row0c * 80 + seg0 * 16,
                          (const char*)(gp[p] + (size_t)row0c * K + k0) + seg0 * 16);
                cpasync16(sb + row1c * 80 + seg1 * 16,
                          (const char*)(gp[p] + (size_t)row1c * K + k0) + seg1 * 16);
            }
            CP_COMMIT();
            CP_WAIT(1);
        } else {
            CP_WAIT(0);
        }
        __syncthreads();

        const uint32_t st   = sbase + cur * STAGE_;
        const uint32_t sA_h = st;
        const uint32_t sA_l = st + PLANE_;
        const uint32_t sB_h = st + 2 * PLANE_;
        const uint32_t sB_l = st + 3 * PLANE_;

#pragma unroll
        for (int ks = 0; ks < 2; ks++) {
            const int kb = ks * 32;   // bytes within row (16 bf16)
            uint32_t ah[2][4], al[2][4], bh[4][4], bl[4][4];
#pragma unroll
            for (int mt = 0; mt < 2; mt++) {
                uint32_t off = (uint32_t)((wm * 32 + mt * 16 + rowA) * 80 + colA + kb);
                LDSM_X4(ah[mt], sA_h + off);
                LDSM_X4(al[mt], sA_l + off);
            }
#pragma unroll
            for (int np = 0; np < 4; np++) {
                uint32_t off = (uint32_t)((wn * 64 + np * 16 + rowB) * 80 + colB + kb);
                LDSM_X4(bh[np], sB_h + off);
                LDSM_X4(bl[np], sB_l + off);
            }
#pragma unroll
            for (int mt = 0; mt < 2; mt++)
#pragma unroll
                for (int nt = 0; nt < 8; nt++) {
                    const uint32_t* ph = &bh[nt >> 1][(nt & 1) * 2];
                    const uint32_t* pl = &bl[nt >> 1][(nt & 1) * 2];
                    MMA16816(acc[mt][nt], ah[mt], ph[0], ph[1]);
                    MMA16816(acc[mt][nt], ah[mt], pl[0], pl[1]);
                    MMA16816(acc[mt][nt], al[mt], ph[0], ph[1]);
                }
        }
        __syncthreads();
    }

    // epilogue
#pragma unroll
    for (int mt = 0; mt < 2; mt++) {
        const int r0 = bm + wm * 32 + mt * 16 + (lane >> 2);
#pragma unroll
        for (int nt = 0; nt < 8; nt++) {
            const int col = bn + wn * 64 + nt * 8 + (lane & 3) * 2;
            *(float2*)&C[(size_t)r0 * N + col] =
                make_float2(acc[mt][nt][0], acc[mt][nt][1]);
            *(float2*)&C[(size_t)(r0 + 8) * N + col] =
                make_float2(acc[mt][nt][2], acc[mt][nt][3]);
        }
    }
}

// ---------------------------------------------------------------------------
// Split fp32 -> bf16 hi + bf16 lo planes
// ---------------------------------------------------------------------------
__global__ void split_kernel(const float* __restrict__ in,
                             __nv_bfloat16* __restrict__ hi,
                             __nv_bfloat16* __restrict__ lo, int n4)
{
    int idx = blockIdx.x * blockDim.x + threadIdx.x;
    if (idx >= n4) return;
    float4 v = ((const float4*)in)[idx];
    __nv_bfloat16 h0 = __float2bfloat16(v.x);
    __nv_bfloat16 h1 = __float2bfloat16(v.y);
    __nv_bfloat16 h2 = __float2bfloat16(v.z);
    __nv_bfloat16 h3 = __float2bfloat16(v.w);
    __nv_bfloat16 l0 = __float2bfloat16(v.x - __bfloat162float(h0));
    __nv_bfloat16 l1 = __float2bfloat16(v.y - __bfloat162float(h1));
    __nv_bfloat16 l2 = __float2bfloat16(v.z - __bfloat162float(h2));
    __nv_bfloat16 l3 = __float2bfloat16(v.w - __bfloat162float(h3));
    __nv_bfloat162* hp = (__nv_bfloat162*)(hi + (size_t)idx * 4);
    __nv_bfloat162* lp = (__nv_bfloat162*)(lo + (size_t)idx * 4);
    hp[0] = __nv_bfloat162(h0, h1); hp[1] = __nv_bfloat162(h2, h3);
    lp[0] = __nv_bfloat162(l0, l1); lp[1] = __nv_bfloat162(l2, l3);
}

// ----------------------------------------------------------------------------
// RoPE in-place on g_qkv (Q heads + K heads), interleaved-pair convention.
// ----------------------------------------------------------------------------
__global__ void rope_kernel(const float* __restrict__ pcos,
                            const float* __restrict__ psin)
{
    int idx = blockIdx.x * blockDim.x + threadIdx.x;
    const int total = M_ * (H_ + KVH_) * (DH_ / 2);
    if (idx >= total) return;
    int i  = idx & 63;
    int h  = (idx >> 6) % (H_ + KVH_);
    int bt = idx / (64 * (H_ + KVH_));
    int t  = bt & (T_ - 1);
    float c = pcos[t * 64 + i];
    float s = psin[t * 64 + i];
    size_t base = (size_t)bt * QKVN_ +
                  ((h < H_) ? (h * DH_) : (QS_ + (h - H_) * DH_)) + 2 * i;
    float v0 = g_qkv[base];
    float v1 = g_qkv[base + 1];
    g_qkv[base]     = v0 * c - v1 * s;
    g_qkv[base + 1] = v0 * s + v1 * c;
}

// ----------------------------------------------------------------------------
// Flash-style causal attention with GQA (reads g_qkv directly, writes g_y).
// ----------------------------------------------------------------------------
#define PAD_ 132
#define ATTN_SMEM (3 * 64 * PAD_ * sizeof(float))

__global__ __launch_bounds__(256, 2) void attn_kernel(float* __restrict__ y)
{
    extern __shared__ float sm[];
    float* sQ = sm;
    float* sK = sQ + 64 * PAD_;
    float* sV = sK + 64 * PAD_;
    float* sP = sK;

    const int tid  = threadIdx.x;
    const int lane = tid & 31;
    const int w    = tid >> 5;
    const int row0 = w * 8;

    const int qb = blockIdx.x * 64;
    const int h  = blockIdx.y;
    const int b  = blockIdx.z;
    const int kh = h >> 2;

    const float* qptr = g_qkv + (size_t)b * T_ * QKVN_ + h * DH_;
    const float* kptr = g_qkv + (size_t)b * T_ * QKVN_ + QS_ + kh * DH_;
    const float* vptr = kptr + KS_;

    for (int i = tid; i < 64 * 32; i += 256) {
        int r  = i >> 5;
        int c4 = (i & 31) << 2;
        *(float4*)&sQ[r * PAD_ + c4] =
            *(const float4*)&qptr[(size_t)(qb + r) * QKVN_ + c4];
    }

    float m_r[8], l_r[8], O[8][4];
#pragma unroll
    for (int r = 0; r < 8; r++) {
        m_r[r] = -1e30f; l_r[r] = 0.0f;
#pragma unroll
        for (int j = 0; j < 4; j++) O[r][j] = 0.0f;
    }

    const float scale = 0.08838834764831845f;
    const int nkb = (qb >> 6) + 1;

    for (int kb = 0; kb < nkb; kb++) {
        for (int i = tid; i < 64 * 32; i += 256) {
            int r  = i >> 5;
            int c4 = (i & 31) << 2;
            size_t grow = (size_t)(kb * 64 + r) * QKVN_ + c4;
            *(float4*)&sK[r * PAD_ + c4] = *(const float4*)&kptr[grow];
            *(float4*)&sV[r * PAD_ + c4] = *(const float4*)&vptr[grow];
        }
        __syncthreads();

        float S[8][2];
#pragma unroll
        for (int r = 0; r < 8; r++) { S[r][0] = 0.0f; S[r][1] = 0.0f; }

        for (int k = 0; k < DH_; k += 4) {
            float4 k0 = *(const float4*)&sK[lane * PAD_ + k];
            float4 k1 = *(const float4*)&sK[(lane + 32) * PAD_ + k];
#pragma unroll
            for (int r = 0; r < 8; r++) {
                float4 q = *(const float4*)&sQ[(row0 + r) * PAD_ + k];
                S[r][0] += q.x * k0.x + q.y * k0.y + q.z * k0.z + q.w * k0.w;
                S[r][1] += q.x * k1.x + q.y * k1.y + q.z * k1.z + q.w * k1.w;
            }
        }
        __syncthreads();

        const bool diag = (kb == (qb >> 6));
#pragma unroll
        for (int r = 0; r < 8; r++) {
            int qrow = qb + row0 + r;
            float s0 = S[r][0] * scale;
            float s1 = S[r][1] * scale;
            if (diag) {
                if (kb * 64 + lane      > qrow) s0 = -1e30f;
                if (kb * 64 + lane + 32 > qrow) s1 = -1e30f;
            }
            float mx = fmaxf(s0, s1);
#pragma unroll
            for (int o = 16; o > 0; o >>= 1)
                mx = fmaxf(mx, __shfl_xor_sync(0xffffffffu, mx, o));
            float mnew = fmaxf(m_r[r], mx);
            float p0 = __expf(s0 - mnew);
            float p1 = __expf(s1 - mnew);
            float corr = __expf(m_r[r] - mnew);
            float ps = p0 + p1;
#pragma unroll
            for (int o = 16; o > 0; o >>= 1)
                ps += __shfl_xor_sync(0xffffffffu, ps, o);
            l_r[r] = l_r[r] * corr + ps;
            m_r[r] = mnew;
#pragma unroll
            for (int j = 0; j < 4; j++) O[r][j] *= corr;
            sP[(row0 + r) * 64 + lane]      = p0;
            sP[(row0 + r) * 64 + lane + 32] = p1;
        }
        __syncwarp();

#pragma unroll 4
        for (int j = 0; j < 64; j++) {
            float v0 = sV[j * PAD_ + lane];
            float v1 = sV[j * PAD_ + lane + 32];
            float v2 = sV[j * PAD_ + lane + 64];
            float v3 = sV[j * PAD_ + lane + 96];
#pragma unroll
            for (int r = 0; r < 8; r++) {
                float p = sP[(row0 + r) * 64 + j];
                O[r][0] += p * v0;
                O[r][1] += p * v1;
                O[r][2] += p * v2;
                O[r][3] += p * v3;
            }
        }
        __syncthreads();
    }

#pragma unroll
    for (int r = 0; r < 8; r++) {
        float inv = 1.0f / l_r[r];
        int t = qb + row0 + r;
        size_t base = ((size_t)(b * T_ + t)) * QS_ + h * DH_;
        y[base + lane]      = O[r][0] * inv;
        y[base + lane + 32] = O[r][1] * inv;
        y[base + lane + 64] = O[r][2] * inv;
        y[base + lane + 96] = O[r][3] * inv;
    }
}

// ----------------------------------------------------------------------------
extern "C" void kernel_launch(void* const* d_in, const int* in_sizes, int n_in,
                              void* d_out, int out_size)
{
    const float* x    = (const float*)d_in[0];
    const float* fcos = (const float*)d_in[1];
    const float* fsin = (const float*)d_in[2];
    const float* wqkv = (const float*)d_in[3];
    const float* wo   = (const float*)d_in[4];
    float* out = (float*)d_out;

    float *qkv = nullptr, *yb = nullptr;
    __nv_bfloat16 *xh, *xl, *wh, *wl, *yh, *yl, *oh, *ol;
    cudaGetSymbolAddress((void**)&qkv, g_qkv);
    cudaGetSymbolAddress((void**)&yb,  g_y);
    cudaGetSymbolAddress((void**)&xh,  g_xh);
    cudaGetSymbolAddress((void**)&xl,  g_xl);
    cudaGetSymbolAddress((void**)&wh,  g_wh);
    cudaGetSymbolAddress((void**)&wl,  g_wl);
    cudaGetSymbolAddress((void**)&yh,  g_yh);
    cudaGetSymbolAddress((void**)&yl,  g_yl);
    cudaGetSymbolAddress((void**)&oh,  g_oh);
    cudaGetSymbolAddress((void**)&ol,  g_ol);

    cudaFuncSetAttribute(gemm3bf16_kernel,
                         cudaFuncAttributeMaxDynamicSharedMemorySize, GSMEM_);
    cudaFuncSetAttribute(attn_kernel,
                         cudaFuncAttributeMaxDynamicSharedMemorySize, (int)ATTN_SMEM);

    // 1) split x and w_qkv to bf16 hi/lo planes
    {
        int n4 = (M_ * D_) / 4;
        split_kernel<<<(n4 + 255) / 256, 256>>>(x, xh, xl, n4);
        n4 = (QKVN_ * D_) / 4;
        split_kernel<<<(n4 + 255) / 256, 256>>>(wqkv, wh, wl, n4);
    }

    // 2) qkv = x @ w_qkv^T
    gemm3bf16_kernel<<<dim3(QKVN_ / 128, M_ / 128), 256, GSMEM_>>>(
        xh, xl, wh, wl, qkv, M_, QKVN_, D_);

    // 3) RoPE in-place
    {
        int total = M_ * (H_ + KVH_) * (DH_ / 2);
        rope_kernel<<<(total + 255) / 256, 256>>>(fcos, fsin);
    }

    // 4) Causal GQA flash attention -> y
    attn_kernel<<<dim3(T_ / 64, H_, B_), 256, ATTN_SMEM>>>(yb);

    // 5) split y and wo
    {
        int n4 = (M_ * QS_) / 4;
        split_kernel<<<(n4 + 255) / 256, 256>>>(yb, yh, yl, n4);
        n4 = (D_ * QS_) / 4;
        split_kernel<<<(n4 + 255) / 256, 256>>>(wo, oh, ol, n4);
    }

    // 6) out = y @ wo^T
    gemm3bf16_kernel<<<dim3(D_ / 128, M_ / 128), 256, GSMEM_>>>(
        yh, yl, oh, ol, out, M_, D_, QS_);
}

// round 5
// speedup vs baseline: 2.4807x; 1.4189x over previous
#include <cuda_runtime.h>
#include <cuda_fp16.h>
#include <cstdint>

#define B_    2
#define T_    2048
#define D_    4096
#define H_    32
#define KVH_  8
#define DH_   128
#define QS_   (H_*DH_)
#define KS_   (KVH_*DH_)
#define QKVN_ (QS_ + 2*KS_)
#define M_    (B_*T_)

// Scratch
__device__ float  g_qkv[(size_t)M_ * QKVN_];
__device__ __half g_xh[(size_t)M_ * D_];
__device__ __half g_xl[(size_t)M_ * D_];
__device__ __half g_wh[(size_t)QKVN_ * D_];
__device__ __half g_wl[(size_t)QKVN_ * D_];
__device__ __half g_oh[(size_t)D_ * QS_];
__device__ __half g_ol[(size_t)D_ * QS_];
__device__ __half g_yh[(size_t)M_ * QS_];
__device__ __half g_yl[(size_t)M_ * QS_];
__device__ __half g_Qh[(size_t)M_ * QS_];
__device__ __half g_Ql[(size_t)M_ * QS_];
__device__ __half g_Kh[(size_t)M_ * KS_];
__device__ __half g_Kl[(size_t)M_ * KS_];
__device__ __half g_Vh[(size_t)M_ * KS_];
__device__ __half g_Vl[(size_t)M_ * KS_];

// ---------------------------------------------------------------------------
__device__ __forceinline__ uint32_t smem_u32(const void* p) {
    uint32_t a;
    asm("{ .reg .u64 t; cvta.to.shared.u64 t, %1; cvt.u32.u64 %0, t; }"
        : "=r"(a) : "l"(p));
    return a;
}
__device__ __forceinline__ void cpasync16(uint32_t s, const void* g) {
    asm volatile("cp.async.cg.shared.global [%0], [%1], 16;" :: "r"(s), "l"(g));
}
#define CP_COMMIT() asm volatile("cp.async.commit_group;" ::: "memory")
#define CP_WAIT(N)  asm volatile("cp.async.wait_group %0;" :: "n"(N) : "memory")

#define LDSM_X4(r, addr)                                                      \
    asm volatile("ldmatrix.sync.aligned.m8n8.x4.shared.b16 {%0,%1,%2,%3}, [%4];" \
        : "=r"((r)[0]), "=r"((r)[1]), "=r"((r)[2]), "=r"((r)[3]) : "r"(addr))
#define LDSM_X4_T(r, addr)                                                    \
    asm volatile("ldmatrix.sync.aligned.m8n8.x4.trans.shared.b16 {%0,%1,%2,%3}, [%4];" \
        : "=r"((r)[0]), "=r"((r)[1]), "=r"((r)[2]), "=r"((r)[3]) : "r"(addr))

#define MMAH(d, a, b0, b1)                                                    \
    asm volatile("mma.sync.aligned.m16n8k16.row.col.f32.f16.f16.f32 "         \
        "{%0,%1,%2,%3}, {%4,%5,%6,%7}, {%8,%9}, {%0,%1,%2,%3};"               \
        : "+f"((d)[0]), "+f"((d)[1]), "+f"((d)[2]), "+f"((d)[3])              \
        : "r"((a)[0]), "r"((a)[1]), "r"((a)[2]), "r"((a)[3]), "r"(b0), "r"(b1))

__device__ __forceinline__ uint32_t packh2(float a, float b) {
    __half2 h = __floats2half2_rn(a, b);
    return *reinterpret_cast<uint32_t*>(&h);
}

// ---------------------------------------------------------------------------
// 3xFP16 mma.sync GEMM:  C = A * B^T, CTA 128x128, BK=32, 256 thr.
// ---------------------------------------------------------------------------
#define PLANE_ (128 * 40 * 2)
#define STAGE_ (4 * PLANE_)
#define GSMEM_ (2 * STAGE_)

__global__ __launch_bounds__(256, 1) void gemm3h_kernel(
    const __half* __restrict__ Ah, const __half* __restrict__ Al,
    const __half* __restrict__ Bh, const __half* __restrict__ Bl,
    float* __restrict__ C, int M, int N, int K)
{
    extern __shared__ char smem[];
    const uint32_t sbase = smem_u32(smem);
    const int tid  = threadIdx.x;
    const int lane = tid & 31;
    const int wid  = tid >> 5;
    const int wm   = wid >> 1;
    const int wn   = wid & 1;

    const int bm = blockIdx.y * 128;
    const int bn = blockIdx.x * 128;
    const int nk = K >> 5;

    const __half* gp[4] = {
        Ah + (size_t)bm * K, Al + (size_t)bm * K,
        Bh + (size_t)bn * K, Bl + (size_t)bn * K };

    const int row0c = tid >> 2, seg0 = tid & 3;
    const int row1c = (tid + 256) >> 2, seg1 = tid & 3;

    float acc[2][8][4];
#pragma unroll
    for (int mt = 0; mt < 2; mt++)
#pragma unroll
        for (int nt = 0; nt < 8; nt++)
#pragma unroll
            for (int q = 0; q < 4; q++) acc[mt][nt][q] = 0.0f;

#pragma unroll
    for (int p = 0; p < 4; p++) {
        uint32_t sb = sbase + p * PLANE_;
        cpasync16(sb + row0c * 80 + seg0 * 16,
                  (const char*)(gp[p] + (size_t)row0c * K) + seg0 * 16);
        cpasync16(sb + row1c * 80 + seg1 * 16,
                  (const char*)(gp[p] + (size_t)row1c * K) + seg1 * 16);
    }
    CP_COMMIT();

    const int rowA = lane & 15;
    const int colA = (lane >> 4) * 16;
    const int rowB = (lane & 7) + ((lane & 16) ? 8 : 0);
    const int colB = ((lane >> 3) & 1) * 16;

    for (int c = 0; c < nk; c++) {
        const int cur = c & 1;
        if (c + 1 < nk) {
            const int k0 = (c + 1) << 5;
            const uint32_t st = sbase + (cur ^ 1) * STAGE_;
#pragma unroll
            for (int p = 0; p < 4; p++) {
                uint32_t sb = st + p * PLANE_;
                cpasync16(sb + row0c * 80 + seg0 * 16,
                          (const char*)(gp[p] + (size_t)row0c * K + k0) + seg0 * 16);
                cpasync16(sb + row1c * 80 + seg1 * 16,
                          (const char*)(gp[p] + (size_t)row1c * K + k0) + seg1 * 16);
            }
            CP_COMMIT();
            CP_WAIT(1);
        } else {
            CP_WAIT(0);
        }
        __syncthreads();

        const uint32_t st   = sbase + cur * STAGE_;
        const uint32_t sA_h = st;
        const uint32_t sA_l = st + PLANE_;
        const uint32_t sB_h = st + 2 * PLANE_;
        const uint32_t sB_l = st + 3 * PLANE_;

#pragma unroll
        for (int ks = 0; ks < 2; ks++) {
            const int kb = ks * 32;
            uint32_t ah[2][4], al[2][4], bh[4][4], bl[4][4];
#pragma unroll
            for (int mt = 0; mt < 2; mt++) {
                uint32_t off = (uint32_t)((wm * 32 + mt * 16 + rowA) * 80 + colA + kb);
                LDSM_X4(ah[mt], sA_h + off);
                LDSM_X4(al[mt], sA_l + off);
            }
#pragma unroll
            for (int np = 0; np < 4; np++) {
                uint32_t off = (uint32_t)((wn * 64 + np * 16 + rowB) * 80 + colB + kb);
                LDSM_X4(bh[np], sB_h + off);
                LDSM_X4(bl[np], sB_l + off);
            }
#pragma unroll
            for (int mt = 0; mt < 2; mt++)
#pragma unroll
                for (int nt = 0; nt < 8; nt++) {
                    const uint32_t* ph = &bh[nt >> 1][(nt & 1) * 2];
                    const uint32_t* pl = &bl[nt >> 1][(nt & 1) * 2];
                    MMAH(acc[mt][nt], ah[mt], ph[0], ph[1]);
                    MMAH(acc[mt][nt], ah[mt], pl[0], pl[1]);
                    MMAH(acc[mt][nt], al[mt], ph[0], ph[1]);
                }
        }
        __syncthreads();
    }

#pragma unroll
    for (int mt = 0; mt < 2; mt++) {
        const int r0 = bm + wm * 32 + mt * 16 + (lane >> 2);
#pragma unroll
        for (int nt = 0; nt < 8; nt++) {
            const int col = bn + wn * 64 + nt * 8 + (lane & 3) * 2;
            *(float2*)&C[(size_t)r0 * N + col] =
                make_float2(acc[mt][nt][0], acc[mt][nt][1]);
            *(float2*)&C[(size_t)(r0 + 8) * N + col] =
                make_float2(acc[mt][nt][2], acc[mt][nt][3]);
        }
    }
}

// ---------------------------------------------------------------------------
// Split fp32 -> fp16 hi/lo
// ---------------------------------------------------------------------------
__global__ void split_kernel(const float* __restrict__ in,
                             __half* __restrict__ hi,
                             __half* __restrict__ lo, int n4)
{
    int idx = blockIdx.x * blockDim.x + threadIdx.x;
    if (idx >= n4) return;
    float4 v = ((const float4*)in)[idx];
    __half h0 = __float2half_rn(v.x), h1 = __float2half_rn(v.y);
    __half h2 = __float2half_rn(v.z), h3 = __float2half_rn(v.w);
    __half2* hp = (__half2*)(hi + (size_t)idx * 4);
    __half2* lp = (__half2*)(lo + (size_t)idx * 4);
    hp[0] = __halves2half2(h0, h1);
    hp[1] = __halves2half2(h2, h3);
    lp[0] = __floats2half2_rn(v.x - __half2float(h0), v.y - __half2float(h1));
    lp[1] = __floats2half2_rn(v.z - __half2float(h2), v.w - __half2float(h3));
}

// ---------------------------------------------------------------------------
// Prep: RoPE + split g_qkv into head-major fp16 planes
// thread handles one float4 (2 rotary pairs)
// ---------------------------------------------------------------------------
__global__ void prep_kernel(const float* __restrict__ pcos,
                            const float* __restrict__ psin)
{
    int idx = blockIdx.x * blockDim.x + threadIdx.x;
    const int total = M_ * 48 * 32;
    if (idx >= total) return;
    int q4 = idx & 31;
    int h  = (idx >> 5) % 48;
    int bt = idx / (32 * 48);
    int t  = bt & (T_ - 1);
    int b  = bt >> 11;

    float4 v = *(const float4*)&g_qkv[(size_t)bt * QKVN_ + h * DH_ + q4 * 4];
    if (h < 40) {
        float2 c = *(const float2*)&pcos[t * 64 + q4 * 2];
        float2 s = *(const float2*)&psin[t * 64 + q4 * 2];
        v = make_float4(v.x * c.x - v.y * s.x, v.x * s.x + v.y * c.x,
                        v.z * c.y - v.w * s.y, v.z * s.y + v.w * c.y);
    }
    __half *ph, *pl;
    size_t off;
    if (h < 32) {
        off = (((size_t)b * H_ + h) * T_ + t) * DH_ + q4 * 4;
        ph = g_Qh; pl = g_Ql;
    } else if (h < 40) {
        off = (((size_t)b * KVH_ + (h - 32)) * T_ + t) * DH_ + q4 * 4;
        ph = g_Kh; pl = g_Kl;
    } else {
        off = (((size_t)b * KVH_ + (h - 40)) * T_ + t) * DH_ + q4 * 4;
        ph = g_Vh; pl = g_Vl;
    }
    __half h0 = __float2half_rn(v.x), h1 = __float2half_rn(v.y);
    __half h2 = __float2half_rn(v.z), h3 = __float2half_rn(v.w);
    ((__half2*)(ph + off))[0] = __halves2half2(h0, h1);
    ((__half2*)(ph + off))[1] = __halves2half2(h2, h3);
    ((__half2*)(pl + off))[0] = __floats2half2_rn(v.x - __half2float(h0), v.y - __half2float(h1));
    ((__half2*)(pl + off))[1] = __floats2half2_rn(v.z - __half2float(h2), v.w - __half2float(h3));
}

// ---------------------------------------------------------------------------
// mma.sync flash attention (causal, GQA), writes yh/yl planes.
// 64 q-rows/CTA, 4 warps, BN=64. smem: Kh|Kl|Vh|Vl 64x128 fp16, stride 272B.
// ---------------------------------------------------------------------------
#define AST_B 272
#define APL_  (64 * AST_B)
#define ASMEM (4 * APL_)

__global__ __launch_bounds__(128, 2) void attn_mma_kernel()
{
    extern __shared__ char sm[];
    const uint32_t sKh = smem_u32(sm);
    const uint32_t sKl = sKh + APL_;
    const uint32_t sVh = sKh + 2 * APL_;
    const uint32_t sVl = sKh + 3 * APL_;

    const int tid = threadIdx.x, lane = tid & 31, w = tid >> 5;
    const int qb = blockIdx.x * 64;
    const int h  = blockIdx.y;
    const int b  = blockIdx.z;
    const int kh = h >> 2;

    const __half* gQh = g_Qh + ((size_t)b * H_ + h) * T_ * DH_;
    const __half* gQl = g_Ql + ((size_t)b * H_ + h) * T_ * DH_;
    const __half* gKh = g_Kh + ((size_t)b * KVH_ + kh) * T_ * DH_;
    const __half* gKl = g_Kl + ((size_t)b * KVH_ + kh) * T_ * DH_;
    const __half* gVh = g_Vh + ((size_t)b * KVH_ + kh) * T_ * DH_;
    const __half* gVl = g_Vl + ((size_t)b * KVH_ + kh) * T_ * DH_;

    // stage Q tile into K buffers, extract frags
#pragma unroll
    for (int k = 0; k < 8; k++) {
        int id = tid + 128 * k, r = id >> 4, sg = id & 15;
        cpasync16(sKh + r * AST_B + sg * 16,
                  (const char*)(gQh + (size_t)(qb + r) * DH_) + sg * 16);
        cpasync16(sKl + r * AST_B + sg * 16,
                  (const char*)(gQl + (size_t)(qb + r) * DH_) + sg * 16);
    }
    CP_COMMIT(); CP_WAIT(0);
    __syncthreads();

    uint32_t qh_[8][4], ql_[8][4];
    {
        uint32_t base = (uint32_t)((w * 16 + (lane & 15)) * AST_B + (lane >> 4) * 16);
#pragma unroll
        for (int ks = 0; ks < 8; ks++) {
            LDSM_X4(qh_[ks], sKh + base + ks * 32);
            LDSM_X4(ql_[ks], sKl + base + ks * 32);
        }
    }
    __syncthreads();

    float o[16][4];
#pragma unroll
    for (int nt = 0; nt < 16; nt++)
#pragma unroll
        for (int q = 0; q < 4; q++) o[nt][q] = 0.0f;
    float m0 = -1e30f, m1 = -1e30f, l0 = 0.0f, l1 = 0.0f;

    const int last = qb >> 6;
    const int rowB = (lane & 7) + ((lane & 16) ? 8 : 0);
    const int colB = ((lane >> 3) & 1) * 16;
    const int qrow0 = qb + w * 16 + (lane >> 2);
    const int qrow1 = qrow0 + 8;
    const float sc = 0.08838834764831845f;

    for (int kb = 0; kb <= last; kb++) {
#pragma unroll
        for (int k = 0; k < 8; k++) {
            int id = tid + 128 * k, r = id >> 4, sg = id & 15;
            size_t grow = (size_t)(kb * 64 + r) * DH_;
            uint32_t soff = (uint32_t)(r * AST_B + sg * 16);
            cpasync16(sKh + soff, (const char*)(gKh + grow) + sg * 16);
            cpasync16(sKl + soff, (const char*)(gKl + grow) + sg * 16);
            cpasync16(sVh + soff, (const char*)(gVh + grow) + sg * 16);
            cpasync16(sVl + soff, (const char*)(gVl + grow) + sg * 16);
        }
        CP_COMMIT(); CP_WAIT(0);
        __syncthreads();

        // S = Q K^T (3-term)
        float s[8][4];
#pragma unroll
        for (int nt = 0; nt < 8; nt++)
#pragma unroll
            for (int q = 0; q < 4; q++) s[nt][q] = 0.0f;

#pragma unroll
        for (int ks = 0; ks < 8; ks++) {
            uint32_t kfh[4][4], kfl[4][4];
#pragma unroll
            for (int pr = 0; pr < 4; pr++) {
                uint32_t off = (uint32_t)((pr * 16 + rowB) * AST_B + colB + ks * 32);
                LDSM_X4(kfh[pr], sKh + off);
                LDSM_X4(kfl[pr], sKl + off);
            }
#pragma unroll
            for (int pr = 0; pr < 4; pr++)
#pragma unroll
                for (int hf = 0; hf < 2; hf++) {
                    int nt = 2 * pr + hf;
                    MMAH(s[nt], qh_[ks], kfh[pr][2 * hf], kfh[pr][2 * hf + 1]);
                    MMAH(s[nt], ql_[ks], kfh[pr][2 * hf], kfh[pr][2 * hf + 1]);
                    MMAH(s[nt], qh_[ks], kfl[pr][2 * hf], kfl[pr][2 * hf + 1]);
                }
        }

        // scale + mask + online softmax
        float mx0 = -1e30f, mx1 = -1e30f;
        const bool dg = (kb == last);
#pragma unroll
        for (int nt = 0; nt < 8; nt++) {
            int c0 = kb * 64 + nt * 8 + 2 * (lane & 3);
#pragma unroll
            for (int q = 0; q < 4; q++) s[nt][q] *= sc;
            if (dg) {
                if (c0     > qrow0) s[nt][0] = -1e30f;
                if (c0 + 1 > qrow0) s[nt][1] = -1e30f;
                if (c0     > qrow1) s[nt][2] = -1e30f;
                if (c0 + 1 > qrow1) s[nt][3] = -1e30f;
            }
            mx0 = fmaxf(mx0, fmaxf(s[nt][0], s[nt][1]));
            mx1 = fmaxf(mx1, fmaxf(s[nt][2], s[nt][3]));
        }
        mx0 = fmaxf(mx0, __shfl_xor_sync(0xffffffffu, mx0, 1));
        mx0 = fmaxf(mx0, __shfl_xor_sync(0xffffffffu, mx0, 2));
        mx1 = fmaxf(mx1, __shfl_xor_sync(0xffffffffu, mx1, 1));
        mx1 = fmaxf(mx1, __shfl_xor_sync(0xffffffffu, mx1, 2));

        float mn0 = fmaxf(m0, mx0), mn1 = fmaxf(m1, mx1);
        float cr0 = __expf(m0 - mn0), cr1 = __expf(m1 - mn1);
        float sum0 = 0.0f, sum1 = 0.0f;
#pragma unroll
        for (int nt = 0; nt < 8; nt++) {
            s[nt][0] = __expf(s[nt][0] - mn0);
            s[nt][1] = __expf(s[nt][1] - mn0);
            s[nt][2] = __expf(s[nt][2] - mn1);
            s[nt][3] = __expf(s[nt][3] - mn1);
            sum0 += s[nt][0] + s[nt][1];
            sum1 += s[nt][2] + s[nt][3];
        }
        sum0 += __shfl_xor_sync(0xffffffffu, sum0, 1);
        sum0 += __shfl_xor_sync(0xffffffffu, sum0, 2);
        sum1 += __shfl_xor_sync(0xffffffffu, sum1, 1);
        sum1 += __shfl_xor_sync(0xffffffffu, sum1, 2);
        l0 = l0 * cr0 + sum0;  m0 = mn0;
        l1 = l1 * cr1 + sum1;  m1 = mn1;
#pragma unroll
        for (int nt = 0; nt < 16; nt++) {
            o[nt][0] *= cr0; o[nt][1] *= cr0;
            o[nt][2] *= cr1; o[nt][3] *= cr1;
        }

        // O += P V (2-term: Ph*Vh + Ph*Vl)
#pragma unroll
        for (int ks = 0; ks < 4; ks++) {
            uint32_t p[4];
            p[0] = packh2(s[2 * ks][0],     s[2 * ks][1]);
            p[1] = packh2(s[2 * ks][2],     s[2 * ks][3]);
            p[2] = packh2(s[2 * ks + 1][0], s[2 * ks + 1][1]);
            p[3] = packh2(s[2 * ks + 1][2], s[2 * ks + 1][3]);
            uint32_t vb = (uint32_t)((ks * 16 + (lane & 15)) * AST_B + (lane >> 4) * 16);
#pragma unroll
            for (int np = 0; np < 8; np++) {
                uint32_t vfh[4], vfl[4];
                LDSM_X4_T(vfh, sVh + vb + np * 32);
                LDSM_X4_T(vfl, sVl + vb + np * 32);
                MMAH(o[2 * np],     p, vfh[0], vfh[1]);
                MMAH(o[2 * np + 1], p, vfh[2], vfh[3]);
                MMAH(o[2 * np],     p, vfl[0], vfl[1]);
                MMAH(o[2 * np + 1], p, vfl[2], vfl[3]);
            }
        }
        __syncthreads();
    }

    // epilogue -> yh/yl planes (token-major [M][QS])
    float i0 = 1.0f / l0, i1 = 1.0f / l1;
    size_t r0 = (size_t)(b * T_ + qb + w * 16 + (lane >> 2)) * QS_ + h * DH_ + 2 * (lane & 3);
    size_t r1 = r0 + (size_t)8 * QS_;
#pragma unroll
    for (int nt = 0; nt < 16; nt++) {
        int cc = nt * 8;
        float a0 = o[nt][0] * i0, a1 = o[nt][1] * i0;
        float b0 = o[nt][2] * i1, b1 = o[nt][3] * i1;
        __half ha0 = __float2half_rn(a0), ha1 = __float2half_rn(a1);
        __half hb0 = __float2half_rn(b0), hb1 = __float2half_rn(b1);
        *(__half2*)(g_yh + r0 + cc) = __halves2half2(ha0, ha1);
        *(__half2*)(g_yl + r0 + cc) =
            __floats2half2_rn(a0 - __half2float(ha0), a1 - __half2float(ha1));
        *(__half2*)(g_yh + r1 + cc) = __halves2half2(hb0, hb1);
        *(__half2*)(g_yl + r1 + cc) =
            __floats2half2_rn(b0 - __half2float(hb0), b1 - __half2float(hb1));
    }
}

// ----------------------------------------------------------------------------
extern "C" void kernel_launch(void* const* d_in, const int* in_sizes, int n_in,
                              void* d_out, int out_size)
{
    const float* x    = (const float*)d_in[0];
    const float* fcos = (const float*)d_in[1];
    const float* fsin = (const float*)d_in[2];
    const float* wqkv = (const float*)d_in[3];
    const float* wo   = (const float*)d_in[4];
    float* out = (float*)d_out;

    float* qkv = nullptr;
    __half *xh, *xl, *wh, *wl, *oh, *ol, *yh, *yl;
    cudaGetSymbolAddress((void**)&qkv, g_qkv);
    cudaGetSymbolAddress((void**)&xh,  g_xh);
    cudaGetSymbolAddress((void**)&xl,  g_xl);
    cudaGetSymbolAddress((void**)&wh,  g_wh);
    cudaGetSymbolAddress((void**)&wl,  g_wl);
    cudaGetSymbolAddress((void**)&oh,  g_oh);
    cudaGetSymbolAddress((void**)&ol,  g_ol);
    cudaGetSymbolAddress((void**)&yh,  g_yh);
    cudaGetSymbolAddress((void**)&yl,  g_yl);

    cudaFuncSetAttribute(gemm3h_kernel,
                         cudaFuncAttributeMaxDynamicSharedMemorySize, GSMEM_);
    cudaFuncSetAttribute(attn_mma_kernel,
                         cudaFuncAttributeMaxDynamicSharedMemorySize, ASMEM);

    // 1) split inputs
    {
        int n4 = (M_ * D_) / 4;
        split_kernel<<<(n4 + 255) / 256, 256>>>(x, xh, xl, n4);
        n4 = (QKVN_ * D_) / 4;
        split_kernel<<<(n4 + 255) / 256, 256>>>(wqkv, wh, wl, n4);
        n4 = (D_ * QS_) / 4;
        split_kernel<<<(n4 + 255) / 256, 256>>>(wo, oh, ol, n4);
    }

    // 2) qkv = x @ w_qkv^T
    gemm3h_kernel<<<dim3(QKVN_ / 128, M_ / 128), 256, GSMEM_>>>(
        xh, xl, wh, wl, qkv, M_, QKVN_, D_);

    // 3) RoPE + split into head-major planes
    {
        int total = M_ * 48 * 32;
        prep_kernel<<<(total + 255) / 256, 256>>>(fcos, fsin);
    }

    // 4) flash attention -> yh/yl
    attn_mma_kernel<<<dim3(T_ / 64, H_, B_), 128, ASMEM>>>();

    // 5) out = y @ wo^T
    gemm3h_kernel<<<dim3(D_ / 128, M_ / 128), 256, GSMEM_>>>(
        yh, yl, oh, ol, out, M_, D_, QS_);
}

// round 6
// speedup vs baseline: 2.9436x; 1.1866x over previous
#include <cuda_runtime.h>
#include <cuda_fp16.h>
#include <cstdint>

#define B_    2
#define T_    2048
#define D_    4096
#define H_    32
#define KVH_  8
#define DH_   128
#define QS_   (H_*DH_)
#define KS_   (KVH_*DH_)
#define QKVN_ (QS_ + 2*KS_)
#define M_    (B_*T_)

// Scratch
__device__ float  g_qkv[(size_t)M_ * QKVN_];
__device__ __half g_xh[(size_t)M_ * D_];
__device__ __half g_xl[(size_t)M_ * D_];
__device__ __half g_wh[(size_t)QKVN_ * D_];
__device__ __half g_wl[(size_t)QKVN_ * D_];
__device__ __half g_oh[(size_t)D_ * QS_];
__device__ __half g_ol[(size_t)D_ * QS_];
__device__ __half g_yh[(size_t)M_ * QS_];
__device__ __half g_yl[(size_t)M_ * QS_];
__device__ __half g_Qh[(size_t)M_ * QS_];
__device__ __half g_Ql[(size_t)M_ * QS_];
__device__ __half g_Kh[(size_t)M_ * KS_];
__device__ __half g_Kl[(size_t)M_ * KS_];
__device__ __half g_Vh[(size_t)M_ * KS_];
__device__ __half g_Vl[(size_t)M_ * KS_];

// ---------------------------------------------------------------------------
__device__ __forceinline__ uint32_t smem_u32(const void* p) {
    uint32_t a;
    asm("{ .reg .u64 t; cvta.to.shared.u64 t, %1; cvt.u32.u64 %0, t; }"
        : "=r"(a) : "l"(p));
    return a;
}
__device__ __forceinline__ void cpasync16(uint32_t s, const void* g) {
    asm volatile("cp.async.cg.shared.global [%0], [%1], 16;" :: "r"(s), "l"(g));
}
#define CP_COMMIT() asm volatile("cp.async.commit_group;" ::: "memory")
#define CP_WAIT(N)  asm volatile("cp.async.wait_group %0;" :: "n"(N) : "memory")

#define LDSM_X4(r, addr)                                                      \
    asm volatile("ldmatrix.sync.aligned.m8n8.x4.shared.b16 {%0,%1,%2,%3}, [%4];" \
        : "=r"((r)[0]), "=r"((r)[1]), "=r"((r)[2]), "=r"((r)[3]) : "r"(addr))
#define LDSM_X4_T(r, addr)                                                    \
    asm volatile("ldmatrix.sync.aligned.m8n8.x4.trans.shared.b16 {%0,%1,%2,%3}, [%4];" \
        : "=r"((r)[0]), "=r"((r)[1]), "=r"((r)[2]), "=r"((r)[3]) : "r"(addr))

#define MMAH(d, a, b0, b1)                                                    \
    asm volatile("mma.sync.aligned.m16n8k16.row.col.f32.f16.f16.f32 "         \
        "{%0,%1,%2,%3}, {%4,%5,%6,%7}, {%8,%9}, {%0,%1,%2,%3};"               \
        : "+f"((d)[0]), "+f"((d)[1]), "+f"((d)[2]), "+f"((d)[3])              \
        : "r"((a)[0]), "r"((a)[1]), "r"((a)[2]), "r"((a)[3]), "r"(b0), "r"(b1))

__device__ __forceinline__ uint32_t packh2(float a, float b) {
    __half2 h = __floats2half2_rn(a, b);
    return *reinterpret_cast<uint32_t*>(&h);
}

// ---------------------------------------------------------------------------
// 3xFP16 mma.sync GEMM:  C = A * B^T, CTA 128x128, BK=32, 256 thr, 2 CTA/SM.
// ---------------------------------------------------------------------------
#define PLANE_ (128 * 40 * 2)
#define STAGE_ (4 * PLANE_)
#define GSMEM_ (2 * STAGE_)

__global__ __launch_bounds__(256, 2) void gemm3h_kernel(
    const __half* __restrict__ Ah, const __half* __restrict__ Al,
    const __half* __restrict__ Bh, const __half* __restrict__ Bl,
    float* __restrict__ C, int M, int N, int K)
{
    extern __shared__ char smem[];
    const uint32_t sbase = smem_u32(smem);
    const int tid  = threadIdx.x;
    const int lane = tid & 31;
    const int wid  = tid >> 5;
    const int wm   = wid >> 1;
    const int wn   = wid & 1;

    const int bm = blockIdx.y * 128;
    const int bn = blockIdx.x * 128;
    const int nk = K >> 5;

    const __half* gp[4] = {
        Ah + (size_t)bm * K, Al + (size_t)bm * K,
        Bh + (size_t)bn * K, Bl + (size_t)bn * K };

    const int row0c = tid >> 2, seg0 = tid & 3;
    const int row1c = (tid + 256) >> 2, seg1 = tid & 3;

    float acc[2][8][4];
#pragma unroll
    for (int mt = 0; mt < 2; mt++)
#pragma unroll
        for (int nt = 0; nt < 8; nt++)
#pragma unroll
            for (int q = 0; q < 4; q++) acc[mt][nt][q] = 0.0f;

#pragma unroll
    for (int p = 0; p < 4; p++) {
        uint32_t sb = sbase + p * PLANE_;
        cpasync16(sb + row0c * 80 + seg0 * 16,
                  (const char*)(gp[p] + (size_t)row0c * K) + seg0 * 16);
        cpasync16(sb + row1c * 80 + seg1 * 16,
                  (const char*)(gp[p] + (size_t)row1c * K) + seg1 * 16);
    }
    CP_COMMIT();

    const int rowA = lane & 15;
    const int colA = (lane >> 4) * 16;
    const int rowB = (lane & 7) + ((lane & 16) ? 8 : 0);
    const int colB = ((lane >> 3) & 1) * 16;

    for (int c = 0; c < nk; c++) {
        const int cur = c & 1;
        if (c + 1 < nk) {
            const int k0 = (c + 1) << 5;
            const uint32_t st = sbase + (cur ^ 1) * STAGE_;
#pragma unroll
            for (int p = 0; p < 4; p++) {
                uint32_t sb = st + p * PLANE_;
                cpasync16(sb + row0c * 80 + seg0 * 16,
                          (const char*)(gp[p] + (size_t)row0c * K + k0) + seg0 * 16);
                cpasync16(sb + row1c * 80 + seg1 * 16,
                          (const char*)(gp[p] + (size_t)row1c * K + k0) + seg1 * 16);
            }
            CP_COMMIT();
            CP_WAIT(1);
        } else {
            CP_WAIT(0);
        }
        __syncthreads();

        const uint32_t st   = sbase + cur * STAGE_;
        const uint32_t sA_h = st;
        const uint32_t sA_l = st + PLANE_;
        const uint32_t sB_h = st + 2 * PLANE_;
        const uint32_t sB_l = st + 3 * PLANE_;

#pragma unroll
        for (int ks = 0; ks < 2; ks++) {
            const int kb = ks * 32;
            uint32_t ah[2][4], al[2][4];
#pragma unroll
            for (int mt = 0; mt < 2; mt++) {
                uint32_t off = (uint32_t)((wm * 32 + mt * 16 + rowA) * 80 + colA + kb);
                LDSM_X4(ah[mt], sA_h + off);
                LDSM_X4(al[mt], sA_l + off);
            }
            // np outer: only one B frag pair (8 regs) live at a time
#pragma unroll
            for (int np = 0; np < 4; np++) {
                uint32_t bh[4], bl[4];
                uint32_t off = (uint32_t)((wn * 64 + np * 16 + rowB) * 80 + colB + kb);
                LDSM_X4(bh, sB_h + off);
                LDSM_X4(bl, sB_l + off);
#pragma unroll
                for (int mt = 0; mt < 2; mt++)
#pragma unroll
                    for (int hf = 0; hf < 2; hf++) {
                        const int nt = 2 * np + hf;
                        MMAH(acc[mt][nt], ah[mt], bh[2 * hf], bh[2 * hf + 1]);
                        MMAH(acc[mt][nt], ah[mt], bl[2 * hf], bl[2 * hf + 1]);
                        MMAH(acc[mt][nt], al[mt], bh[2 * hf], bh[2 * hf + 1]);
                    }
            }
        }
        __syncthreads();
    }

#pragma unroll
    for (int mt = 0; mt < 2; mt++) {
        const int r0 = bm + wm * 32 + mt * 16 + (lane >> 2);
#pragma unroll
        for (int nt = 0; nt < 8; nt++) {
            const int col = bn + wn * 64 + nt * 8 + (lane & 3) * 2;
            *(float2*)&C[(size_t)r0 * N + col] =
                make_float2(acc[mt][nt][0], acc[mt][nt][1]);
            *(float2*)&C[(size_t)(r0 + 8) * N + col] =
                make_float2(acc[mt][nt][2], acc[mt][nt][3]);
        }
    }
}

// ---------------------------------------------------------------------------
// Split fp32 -> fp16 hi/lo
// ---------------------------------------------------------------------------
__global__ void split_kernel(const float* __restrict__ in,
                             __half* __restrict__ hi,
                             __half* __restrict__ lo, int n4)
{
    int idx = blockIdx.x * blockDim.x + threadIdx.x;
    if (idx >= n4) return;
    float4 v = ((const float4*)in)[idx];
    __half h0 = __float2half_rn(v.x), h1 = __float2half_rn(v.y);
    __half h2 = __float2half_rn(v.z), h3 = __float2half_rn(v.w);
    __half2* hp = (__half2*)(hi + (size_t)idx * 4);
    __half2* lp = (__half2*)(lo + (size_t)idx * 4);
    hp[0] = __halves2half2(h0, h1);
    hp[1] = __halves2half2(h2, h3);
    lp[0] = __floats2half2_rn(v.x - __half2float(h0), v.y - __half2float(h1));
    lp[1] = __floats2half2_rn(v.z - __half2float(h2), v.w - __half2float(h3));
}

// ---------------------------------------------------------------------------
// Prep: RoPE + split g_qkv into head-major fp16 planes
// ---------------------------------------------------------------------------
__global__ void prep_kernel(const float* __restrict__ pcos,
                            const float* __restrict__ psin)
{
    int idx = blockIdx.x * blockDim.x + threadIdx.x;
    const int total = M_ * 48 * 32;
    if (idx >= total) return;
    int q4 = idx & 31;
    int h  = (idx >> 5) % 48;
    int bt = idx / (32 * 48);
    int t  = bt & (T_ - 1);
    int b  = bt >> 11;

    float4 v = *(const float4*)&g_qkv[(size_t)bt * QKVN_ + h * DH_ + q4 * 4];
    if (h < 40) {
        float2 c = *(const float2*)&pcos[t * 64 + q4 * 2];
        float2 s = *(const float2*)&psin[t * 64 + q4 * 2];
        v = make_float4(v.x * c.x - v.y * s.x, v.x * s.x + v.y * c.x,
                        v.z * c.y - v.w * s.y, v.z * s.y + v.w * c.y);
    }
    __half *ph, *pl;
    size_t off;
    if (h < 32) {
        off = (((size_t)b * H_ + h) * T_ + t) * DH_ + q4 * 4;
        ph = g_Qh; pl = g_Ql;
    } else if (h < 40) {
        off = (((size_t)b * KVH_ + (h - 32)) * T_ + t) * DH_ + q4 * 4;
        ph = g_Kh; pl = g_Kl;
    } else {
        off = (((size_t)b * KVH_ + (h - 40)) * T_ + t) * DH_ + q4 * 4;
        ph = g_Vh; pl = g_Vl;
    }
    __half h0 = __float2half_rn(v.x), h1 = __float2half_rn(v.y);
    __half h2 = __float2half_rn(v.z), h3 = __float2half_rn(v.w);
    ((__half2*)(ph + off))[0] = __halves2half2(h0, h1);
    ((__half2*)(ph + off))[1] = __halves2half2(h2, h3);
    ((__half2*)(pl + off))[0] = __floats2half2_rn(v.x - __half2float(h0), v.y - __half2float(h1));
    ((__half2*)(pl + off))[1] = __floats2half2_rn(v.z - __half2float(h2), v.w - __half2float(h3));
}

// ---------------------------------------------------------------------------
// mma.sync flash attention (causal, GQA), writes yh/yl planes.
// ---------------------------------------------------------------------------
#define AST_B 272
#define APL_  (64 * AST_B)
#define ASMEM (4 * APL_)

__global__ __launch_bounds__(128, 2) void attn_mma_kernel()
{
    extern __shared__ char sm[];
    const uint32_t sKh = smem_u32(sm);
    const uint32_t sKl = sKh + APL_;
    const uint32_t sVh = sKh + 2 * APL_;
    const uint32_t sVl = sKh + 3 * APL_;

    const int tid = threadIdx.x, lane = tid & 31, w = tid >> 5;
    const int qb = blockIdx.x * 64;
    const int h  = blockIdx.y;
    const int b  = blockIdx.z;
    const int kh = h >> 2;

    const __half* gQh = g_Qh + ((size_t)b * H_ + h) * T_ * DH_;
    const __half* gQl = g_Ql + ((size_t)b * H_ + h) * T_ * DH_;
    const __half* gKh = g_Kh + ((size_t)b * KVH_ + kh) * T_ * DH_;
    const __half* gKl = g_Kl + ((size_t)b * KVH_ + kh) * T_ * DH_;
    const __half* gVh = g_Vh + ((size_t)b * KVH_ + kh) * T_ * DH_;
    const __half* gVl = g_Vl + ((size_t)b * KVH_ + kh) * T_ * DH_;

#pragma unroll
    for (int k = 0; k < 8; k++) {
        int id = tid + 128 * k, r = id >> 4, sg = id & 15;
        cpasync16(sKh + r * AST_B + sg * 16,
                  (const char*)(gQh + (size_t)(qb + r) * DH_) + sg * 16);
        cpasync16(sKl + r * AST_B + sg * 16,
                  (const char*)(gQl + (size_t)(qb + r) * DH_) + sg * 16);
    }
    CP_COMMIT(); CP_WAIT(0);
    __syncthreads();

    uint32_t qh_[8][4], ql_[8][4];
    {
        uint32_t base = (uint32_t)((w * 16 + (lane & 15)) * AST_B + (lane >> 4) * 16);
#pragma unroll
        for (int ks = 0; ks < 8; ks++) {
            LDSM_X4(qh_[ks], sKh + base + ks * 32);
            LDSM_X4(ql_[ks], sKl + base + ks * 32);
        }
    }
    __syncthreads();

    float o[16][4];
#pragma unroll
    for (int nt = 0; nt < 16; nt++)
#pragma unroll
        for (int q = 0; q < 4; q++) o[nt][q] = 0.0f;
    float m0 = -1e30f, m1 = -1e30f, l0 = 0.0f, l1 = 0.0f;

    const int last = qb >> 6;
    const int rowB = (lane & 7) + ((lane & 16) ? 8 : 0);
    const int colB = ((lane >> 3) & 1) * 16;
    const int qrow0 = qb + w * 16 + (lane >> 2);
    const int qrow1 = qrow0 + 8;
    const float sc = 0.08838834764831845f;

    for (int kb = 0; kb <= last; kb++) {
#pragma unroll
        for (int k = 0; k < 8; k++) {
            int id = tid + 128 * k, r = id >> 4, sg = id & 15;
            size_t grow = (size_t)(kb * 64 + r) * DH_;
            uint32_t soff = (uint32_t)(r * AST_B + sg * 16);
            cpasync16(sKh + soff, (const char*)(gKh + grow) + sg * 16);
            cpasync16(sKl + soff, (const char*)(gKl + grow) + sg * 16);
            cpasync16(sVh + soff, (const char*)(gVh + grow) + sg * 16);
            cpasync16(sVl + soff, (const char*)(gVl + grow) + sg * 16);
        }
        CP_COMMIT(); CP_WAIT(0);
        __syncthreads();

        float s[8][4];
#pragma unroll
        for (int nt = 0; nt < 8; nt++)
#pragma unroll
            for (int q = 0; q < 4; q++) s[nt][q] = 0.0f;

#pragma unroll
        for (int ks = 0; ks < 8; ks++) {
            uint32_t kfh[4][4], kfl[4][4];
#pragma unroll
            for (int pr = 0; pr < 4; pr++) {
                uint32_t off = (uint32_t)((pr * 16 + rowB) * AST_B + colB + ks * 32);
                LDSM_X4(kfh[pr], sKh + off);
                LDSM_X4(kfl[pr], sKl + off);
            }
#pragma unroll
            for (int pr = 0; pr < 4; pr++)
#pragma unroll
                for (int hf = 0; hf < 2; hf++) {
                    int nt = 2 * pr + hf;
                    MMAH(s[nt], qh_[ks], kfh[pr][2 * hf], kfh[pr][2 * hf + 1]);
                    MMAH(s[nt], ql_[ks], kfh[pr][2 * hf], kfh[pr][2 * hf + 1]);
                    MMAH(s[nt], qh_[ks], kfl[pr][2 * hf], kfl[pr][2 * hf + 1]);
                }
        }

        float mx0 = -1e30f, mx1 = -1e30f;
        const bool dg = (kb == last);
#pragma unroll
        for (int nt = 0; nt < 8; nt++) {
            int c0 = kb * 64 + nt * 8 + 2 * (lane & 3);
#pragma unroll
            for (int q = 0; q < 4; q++) s[nt][q] *= sc;
            if (dg) {
                if (c0     > qrow0) s[nt][0] = -1e30f;
                if (c0 + 1 > qrow0) s[nt][1] = -1e30f;
                if (c0     > qrow1) s[nt][2] = -1e30f;
                if (c0 + 1 > qrow1) s[nt][3] = -1e30f;
            }
            mx0 = fmaxf(mx0, fmaxf(s[nt][0], s[nt][1]));
            mx1 = fmaxf(mx1, fmaxf(s[nt][2], s[nt][3]));
        }
        mx0 = fmaxf(mx0, __shfl_xor_sync(0xffffffffu, mx0, 1));
        mx0 = fmaxf(mx0, __shfl_xor_sync(0xffffffffu, mx0, 2));
        mx1 = fmaxf(mx1, __shfl_xor_sync(0xffffffffu, mx1, 1));
        mx1 = fmaxf(mx1, __shfl_xor_sync(0xffffffffu, mx1, 2));

        float mn0 = fmaxf(m0, mx0), mn1 = fmaxf(m1, mx1);
        float cr0 = __expf(m0 - mn0), cr1 = __expf(m1 - mn1);
        float sum0 = 0.0f, sum1 = 0.0f;
#pragma unroll
        for (int nt = 0; nt < 8; nt++) {
            s[nt][0] = __expf(s[nt][0] - mn0);
            s[nt][1] = __expf(s[nt][1] - mn0);
            s[nt][2] = __expf(s[nt][2] - mn1);
            s[nt][3] = __expf(s[nt][3] - mn1);
            sum0 += s[nt][0] + s[nt][1];
            sum1 += s[nt][2] + s[nt][3];
        }
        sum0 += __shfl_xor_sync(0xffffffffu, sum0, 1);
        sum0 += __shfl_xor_sync(0xffffffffu, sum0, 2);
        sum1 += __shfl_xor_sync(0xffffffffu, sum1, 1);
        sum1 += __shfl_xor_sync(0xffffffffu, sum1, 2);
        l0 = l0 * cr0 + sum0;  m0 = mn0;
        l1 = l1 * cr1 + sum1;  m1 = mn1;
#pragma unroll
        for (int nt = 0; nt < 16; nt++) {
            o[nt][0] *= cr0; o[nt][1] *= cr0;
            o[nt][2] *= cr1; o[nt][3] *= cr1;
        }

#pragma unroll
        for (int ks = 0; ks < 4; ks++) {
            uint32_t p[4];
            p[0] = packh2(s[2 * ks][0],     s[2 * ks][1]);
            p[1] = packh2(s[2 * ks][2],     s[2 * ks][3]);
            p[2] = packh2(s[2 * ks + 1][0], s[2 * ks + 1][1]);
            p[3] = packh2(s[2 * ks + 1][2], s[2 * ks + 1][3]);
            uint32_t vb = (uint32_t)((ks * 16 + (lane & 15)) * AST_B + (lane >> 4) * 16);
#pragma unroll
            for (int np = 0; np < 8; np++) {
                uint32_t vfh[4], vfl[4];
                LDSM_X4_T(vfh, sVh + vb + np * 32);
                LDSM_X4_T(vfl, sVl + vb + np * 32);
                MMAH(o[2 * np],     p, vfh[0], vfh[1]);
                MMAH(o[2 * np + 1], p, vfh[2], vfh[3]);
                MMAH(o[2 * np],     p, vfl[0], vfl[1]);
                MMAH(o[2 * np + 1], p, vfl[2], vfl[3]);
            }
        }
        __syncthreads();
    }

    float i0 = 1.0f / l0, i1 = 1.0f / l1;
    size_t r0 = (size_t)(b * T_ + qb + w * 16 + (lane >> 2)) * QS_ + h * DH_ + 2 * (lane & 3);
    size_t r1 = r0 + (size_t)8 * QS_;
#pragma unroll
    for (int nt = 0; nt < 16; nt++) {
        int cc = nt * 8;
        float a0 = o[nt][0] * i0, a1 = o[nt][1] * i0;
        float b0 = o[nt][2] * i1, b1 = o[nt][3] * i1;
        __half ha0 = __float2half_rn(a0), ha1 = __float2half_rn(a1);
        __half hb0 = __float2half_rn(b0), hb1 = __float2half_rn(b1);
        *(__half2*)(g_yh + r0 + cc) = __halves2half2(ha0, ha1);
        *(__half2*)(g_yl + r0 + cc) =
            __floats2half2_rn(a0 - __half2float(ha0), a1 - __half2float(ha1));
        *(__half2*)(g_yh + r1 + cc) = __halves2half2(hb0, hb1);
        *(__half2*)(g_yl + r1 + cc) =
            __floats2half2_rn(b0 - __half2float(hb0), b1 - __half2float(hb1));
    }
}

// ----------------------------------------------------------------------------
extern "C" void kernel_launch(void* const* d_in, const int* in_sizes, int n_in,
                              void* d_out, int out_size)
{
    const float* x    = (const float*)d_in[0];
    const float* fcos = (const float*)d_in[1];
    const float* fsin = (const float*)d_in[2];
    const float* wqkv = (const float*)d_in[3];
    const float* wo   = (const float*)d_in[4];
    float* out = (float*)d_out;

    float* qkv = nullptr;
    __half *xh, *xl, *wh, *wl, *oh, *ol, *yh, *yl;
    cudaGetSymbolAddress((void**)&qkv, g_qkv);
    cudaGetSymbolAddress((void**)&xh,  g_xh);
    cudaGetSymbolAddress((void**)&xl,  g_xl);
    cudaGetSymbolAddress((void**)&wh,  g_wh);
    cudaGetSymbolAddress((void**)&wl,  g_wl);
    cudaGetSymbolAddress((void**)&oh,  g_oh);
    cudaGetSymbolAddress((void**)&ol,  g_ol);
    cudaGetSymbolAddress((void**)&yh,  g_yh);
    cudaGetSymbolAddress((void**)&yl,  g_yl);

    cudaFuncSetAttribute(gemm3h_kernel,
                         cudaFuncAttributeMaxDynamicSharedMemorySize, GSMEM_);
    cudaFuncSetAttribute(attn_mma_kernel,
                         cudaFuncAttributeMaxDynamicSharedMemorySize, ASMEM);

    {
        int n4 = (M_ * D_) / 4;
        split_kernel<<<(n4 + 255) / 256, 256>>>(x, xh, xl, n4);
        n4 = (QKVN_ * D_) / 4;
        split_kernel<<<(n4 + 255) / 256, 256>>>(wqkv, wh, wl, n4);
        n4 = (D_ * QS_) / 4;
        split_kernel<<<(n4 + 255) / 256, 256>>>(wo, oh, ol, n4);
    }

    gemm3h_kernel<<<dim3(QKVN_ / 128, M_ / 128), 256, GSMEM_>>>(
        xh, xl, wh, wl, qkv, M_, QKVN_, D_);

    {
        int total = M_ * 48 * 32;
        prep_kernel<<<(total + 255) / 256, 256>>>(fcos, fsin);
    }

    attn_mma_kernel<<<dim3(T_ / 64, H_, B_), 128, ASMEM>>>();

    gemm3h_kernel<<<dim3(D_ / 128, M_ / 128), 256, GSMEM_>>>(
        yh, yl, oh, ol, out, M_, D_, QS_);
}